// round 1
// baseline (speedup 1.0000x reference)
#include <cuda_runtime.h>
#include <math.h>

#define HID   1024
#define BATCH 4
#define SEQ   2048

#define BM 128
#define BN 128
#define BK 8

// Device scratch (no allocations allowed in kernel_launch)
__device__ float g_q[(long long)BATCH * SEQ * HID];
__device__ float g_k[(long long)BATCH * SEQ * HID];
__device__ float g_v[(long long)BATCH * SEQ * HID];
__device__ float g_l[BATCH * SEQ];
__device__ float g_attn[(long long)BATCH * SEQ * SEQ];

// ---------------------------------------------------------------------------
// NT GEMM: C[m,n] = scale * sum_k A[m,k]*B[n,k] + bias[n]
// A: M x K row-major, B: N x K row-major. Used for projections and scores.
// causal: skip blocks fully below the diagonal (m = key index s, n = query t)
// ---------------------------------------------------------------------------
__global__ __launch_bounds__(256)
void gemm_nt(const float* __restrict__ A, const float* __restrict__ B,
             const float* __restrict__ bias, float* __restrict__ C,
             int M, int N, int K, float scale, int causal,
             long long strideA, long long strideB, long long strideC)
{
    int m0 = blockIdx.y * BM;
    int n0 = blockIdx.x * BN;
    if (causal && m0 > n0 + BN - 1) return;   // fully masked score block

    A += (long long)blockIdx.z * strideA;
    B += (long long)blockIdx.z * strideB;
    C += (long long)blockIdx.z * strideC;

    __shared__ __align__(16) float As[BK][BM + 4];
    __shared__ __align__(16) float Bs[BK][BN + 4];

    int tid = threadIdx.x;
    int tx = tid & 15;       // n direction (8 cols each)
    int ty = tid >> 4;       // m direction (8 rows each)
    int lrow = tid >> 1;     // 0..127
    int lk   = (tid & 1) * 4;

    const float* Ag = A + (long long)(m0 + lrow) * K + lk;
    const float* Bg = B + (long long)(n0 + lrow) * K + lk;

    float acc[8][8];
    #pragma unroll
    for (int i = 0; i < 8; ++i)
        #pragma unroll
        for (int j = 0; j < 8; ++j) acc[i][j] = 0.f;

    for (int k0 = 0; k0 < K; k0 += BK) {
        float4 av = *(const float4*)(Ag + k0);
        float4 bv = *(const float4*)(Bg + k0);
        As[lk + 0][lrow] = av.x; As[lk + 1][lrow] = av.y;
        As[lk + 2][lrow] = av.z; As[lk + 3][lrow] = av.w;
        Bs[lk + 0][lrow] = bv.x; Bs[lk + 1][lrow] = bv.y;
        Bs[lk + 2][lrow] = bv.z; Bs[lk + 3][lrow] = bv.w;
        __syncthreads();

        #pragma unroll
        for (int kk = 0; kk < BK; ++kk) {
            float4 a0 = *(const float4*)&As[kk][ty * 8];
            float4 a1 = *(const float4*)&As[kk][ty * 8 + 4];
            float4 b0 = *(const float4*)&Bs[kk][tx * 8];
            float4 b1 = *(const float4*)&Bs[kk][tx * 8 + 4];
            float a[8] = {a0.x, a0.y, a0.z, a0.w, a1.x, a1.y, a1.z, a1.w};
            float b[8] = {b0.x, b0.y, b0.z, b0.w, b1.x, b1.y, b1.z, b1.w};
            #pragma unroll
            for (int i = 0; i < 8; ++i)
                #pragma unroll
                for (int j = 0; j < 8; ++j)
                    acc[i][j] += a[i] * b[j];
        }
        __syncthreads();
    }

    float bb[8];
    if (bias) {
        float4 b0 = *(const float4*)(bias + n0 + tx * 8);
        float4 b1 = *(const float4*)(bias + n0 + tx * 8 + 4);
        bb[0]=b0.x; bb[1]=b0.y; bb[2]=b0.z; bb[3]=b0.w;
        bb[4]=b1.x; bb[5]=b1.y; bb[6]=b1.z; bb[7]=b1.w;
    } else {
        #pragma unroll
        for (int j = 0; j < 8; ++j) bb[j] = 0.f;
    }

    #pragma unroll
    for (int i = 0; i < 8; ++i) {
        float4 o0, o1;
        o0.x = acc[i][0] * scale + bb[0];
        o0.y = acc[i][1] * scale + bb[1];
        o0.z = acc[i][2] * scale + bb[2];
        o0.w = acc[i][3] * scale + bb[3];
        o1.x = acc[i][4] * scale + bb[4];
        o1.y = acc[i][5] * scale + bb[5];
        o1.z = acc[i][6] * scale + bb[6];
        o1.w = acc[i][7] * scale + bb[7];
        float* Cp = C + (long long)(m0 + ty * 8 + i) * N + n0 + tx * 8;
        *(float4*)(Cp)     = o0;
        *(float4*)(Cp + 4) = o1;
    }
}

// ---------------------------------------------------------------------------
// TN GEMM: C[m,n] = sum_k A[k,m]*B[k,n]   (context = attn^T @ V)
// A: K x M row-major (lda), B: K x N row-major (ldb).
// kLimitCausal: restrict K loop to m0+BM (attn rows with s>t are zero anyway)
// ---------------------------------------------------------------------------
__global__ __launch_bounds__(256)
void gemm_tn(const float* __restrict__ A, const float* __restrict__ B,
             float* __restrict__ C,
             int M, int N, int K, int lda, int ldb, int kLimitCausal,
             long long strideA, long long strideB, long long strideC)
{
    int m0 = blockIdx.y * BM;
    int n0 = blockIdx.x * BN;
    A += (long long)blockIdx.z * strideA;
    B += (long long)blockIdx.z * strideB;
    C += (long long)blockIdx.z * strideC;

    int Kend = kLimitCausal ? min(K, m0 + BM) : K;

    __shared__ __align__(16) float As[BK][BM];
    __shared__ __align__(16) float Bs[BK][BN];

    int tid = threadIdx.x;
    int tx = tid & 15;
    int ty = tid >> 4;
    int lk2  = tid >> 5;          // 0..7
    int lcol = (tid & 31) * 4;    // 0..124

    float acc[8][8];
    #pragma unroll
    for (int i = 0; i < 8; ++i)
        #pragma unroll
        for (int j = 0; j < 8; ++j) acc[i][j] = 0.f;

    for (int k0 = 0; k0 < Kend; k0 += BK) {
        float4 av = *(const float4*)(A + (long long)(k0 + lk2) * lda + m0 + lcol);
        float4 bv = *(const float4*)(B + (long long)(k0 + lk2) * ldb + n0 + lcol);
        *(float4*)&As[lk2][lcol] = av;
        *(float4*)&Bs[lk2][lcol] = bv;
        __syncthreads();

        #pragma unroll
        for (int kk = 0; kk < BK; ++kk) {
            float4 a0 = *(const float4*)&As[kk][ty * 8];
            float4 a1 = *(const float4*)&As[kk][ty * 8 + 4];
            float4 b0 = *(const float4*)&Bs[kk][tx * 8];
            float4 b1 = *(const float4*)&Bs[kk][tx * 8 + 4];
            float a[8] = {a0.x, a0.y, a0.z, a0.w, a1.x, a1.y, a1.z, a1.w};
            float b[8] = {b0.x, b0.y, b0.z, b0.w, b1.x, b1.y, b1.z, b1.w};
            #pragma unroll
            for (int i = 0; i < 8; ++i)
                #pragma unroll
                for (int j = 0; j < 8; ++j)
                    acc[i][j] += a[i] * b[j];
        }
        __syncthreads();
    }

    #pragma unroll
    for (int i = 0; i < 8; ++i) {
        float4 o0 = {acc[i][0], acc[i][1], acc[i][2], acc[i][3]};
        float4 o1 = {acc[i][4], acc[i][5], acc[i][6], acc[i][7]};
        float* Cp = C + (long long)(m0 + ty * 8 + i) * N + n0 + tx * 8;
        *(float4*)(Cp)     = o0;
        *(float4*)(Cp + 4) = o1;
    }
}

// ---------------------------------------------------------------------------
// Softmax over key dim s (column-wise in the (s,t) score matrix).
// No max subtraction needed: scores are O(1); masked -> exact 0 (matches ref,
// where exp(score - 1e7 - max) underflows to 0.0f).
// ---------------------------------------------------------------------------
#define SCHUNK (SEQ / 8)

__global__ void softmax_pass1(float* __restrict__ att, float* __restrict__ lsum)
{
    int t  = blockIdx.x * blockDim.x + threadIdx.x;
    int b  = blockIdx.z;
    int s0 = blockIdx.y * SCHUNK;
    int tmax = blockIdx.x * blockDim.x + blockDim.x - 1;

    float* base = att + (long long)b * SEQ * SEQ + (long long)s0 * SEQ + t;

    if (s0 > tmax) {            // chunk fully masked: just write zeros
        #pragma unroll 4
        for (int i = 0; i < SCHUNK; ++i)
            base[(long long)i * SEQ] = 0.f;
        return;
    }

    float l0 = 0.f, l1 = 0.f, l2 = 0.f, l3 = 0.f;
    for (int i = 0; i < SCHUNK; i += 4) {
        #pragma unroll
        for (int u = 0; u < 4; ++u) {
            int s = s0 + i + u;
            float vv = base[(long long)(i + u) * SEQ];
            float e = (s <= t) ? __expf(vv) : 0.f;
            base[(long long)(i + u) * SEQ] = e;
            if (u == 0) l0 += e; else if (u == 1) l1 += e;
            else if (u == 2) l2 += e; else l3 += e;
        }
    }
    atomicAdd(&lsum[b * SEQ + t], (l0 + l1) + (l2 + l3));
}

__global__ void softmax_pass2(float* __restrict__ att, const float* __restrict__ lsum)
{
    int t  = blockIdx.x * blockDim.x + threadIdx.x;
    int b  = blockIdx.z;
    int s0 = blockIdx.y * SCHUNK;
    int tmax = blockIdx.x * blockDim.x + blockDim.x - 1;
    if (s0 > tmax) return;      // already exact zeros

    float inv = 1.0f / lsum[b * SEQ + t];
    float* base = att + (long long)b * SEQ * SEQ + (long long)s0 * SEQ + t;
    #pragma unroll 4
    for (int i = 0; i < SCHUNK; ++i)
        base[(long long)i * SEQ] *= inv;
}

// ---------------------------------------------------------------------------
// Launch
// ---------------------------------------------------------------------------
extern "C" void kernel_launch(void* const* d_in, const int* in_sizes, int n_in,
                              void* d_out, int out_size)
{
    const float* xq = (const float*)d_in[0];
    const float* xk = (const float*)d_in[1];
    const float* xv = (const float*)d_in[2];
    const float* Wq = (const float*)d_in[3];
    const float* bq = (const float*)d_in[4];
    const float* Wk = (const float*)d_in[5];
    const float* bk = (const float*)d_in[6];
    const float* Wv = (const float*)d_in[7];
    const float* bv = (const float*)d_in[8];
    float* out = (float*)d_out;

    float *q, *k, *v, *lsum, *attnScratch;
    cudaGetSymbolAddress((void**)&q, g_q);
    cudaGetSymbolAddress((void**)&k, g_k);
    cudaGetSymbolAddress((void**)&v, g_v);
    cudaGetSymbolAddress((void**)&lsum, g_l);
    cudaGetSymbolAddress((void**)&attnScratch, g_attn);

    const long long ctxElems  = (long long)BATCH * SEQ * HID;   //  8388608
    const long long attnElems = (long long)BATCH * SEQ * SEQ;   // 16777216
    float* ctx  = out;
    float* attn = ((long long)out_size >= ctxElems + attnElems) ? (out + ctxElems)
                                                                : attnScratch;

    const int MProj = BATCH * SEQ;            // 8192
    const float scale = 0.03125f;             // 1/sqrt(1024)
    dim3 blk(256);

    // Projections: Q/K/V = X @ W^T + b
    gemm_nt<<<dim3(HID / BN, MProj / BM), blk>>>(xq, Wq, bq, q, MProj, HID, HID, 1.f, 0, 0, 0, 0);
    gemm_nt<<<dim3(HID / BN, MProj / BM), blk>>>(xk, Wk, bk, k, MProj, HID, HID, 1.f, 0, 0, 0, 0);
    gemm_nt<<<dim3(HID / BN, MProj / BM), blk>>>(xv, Wv, bv, v, MProj, HID, HID, 1.f, 0, 0, 0, 0);

    // Scores[b,s,t] = scale * <K_s, Q_t>  (skip fully-masked blocks)
    gemm_nt<<<dim3(SEQ / BN, SEQ / BM, BATCH), blk>>>(
        k, q, nullptr, attn, SEQ, SEQ, HID, scale, 1,
        (long long)SEQ * HID, (long long)SEQ * HID, (long long)SEQ * SEQ);

    // Softmax over s
    cudaMemsetAsync(lsum, 0, BATCH * SEQ * sizeof(float), 0);
    softmax_pass1<<<dim3(SEQ / 256, 8, BATCH), 256>>>(attn, lsum);
    softmax_pass2<<<dim3(SEQ / 256, 8, BATCH), 256>>>(attn, lsum);

    // Context[b,t,h] = sum_s attn[b,s,t] * V[b,s,h]  (K loop truncated at diag)
    gemm_tn<<<dim3(HID / BN, SEQ / BM, BATCH), blk>>>(
        attn, v, ctx, SEQ, HID, SEQ, SEQ, HID, 1,
        (long long)SEQ * SEQ, (long long)SEQ * HID, (long long)SEQ * HID);
}

// round 7
// speedup vs baseline: 2.3873x; 2.3873x over previous
#include <cuda_runtime.h>
#include <cuda_fp16.h>
#include <cstdint>

#define SEQ   2048
#define HID   1024
#define BATCH 4
#define RALL  (BATCH*SEQ)          // 8192

// ---------------- device scratch --------------------------------------------
__device__ __align__(16) __half g_xh[3][(long long)RALL*HID];
__device__ __align__(16) __half g_xl[3][(long long)RALL*HID];
__device__ __align__(16) __half g_wh[3][HID*HID];
__device__ __align__(16) __half g_wl[3][HID*HID];
__device__ __align__(16) __half g_qh[(long long)RALL*HID], g_ql[(long long)RALL*HID];
__device__ __align__(16) __half g_kh[(long long)RALL*HID], g_kl[(long long)RALL*HID];
__device__ float g_vf[(long long)RALL*HID];
__device__ __align__(16) __half g_vth[(long long)RALL*HID], g_vtl[(long long)RALL*HID];
__device__ __align__(16) __half g_ath[(long long)BATCH*SEQ*SEQ], g_atl[(long long)BATCH*SEQ*SEQ];
__device__ float g_attn[(long long)BATCH*SEQ*SEQ];
__device__ float g_l[BATCH*SEQ];

// ---------------- low-level helpers -----------------------------------------
__device__ __forceinline__ uint32_t smem_u32(const void* p){
    uint32_t a;
    asm("{ .reg .u64 t; cvta.to.shared.u64 t, %1; cvt.u32.u64 %0, t; }" : "=r"(a) : "l"(p));
    return a;
}
__device__ __forceinline__ void cp16(uint32_t d, const void* g){
    asm volatile("cp.async.cg.shared.global [%0], [%1], 16;" :: "r"(d), "l"(g));
}
__device__ __forceinline__ void ldm4(uint32_t* r, uint32_t a){
    asm volatile("ldmatrix.sync.aligned.m8n8.x4.shared.b16 {%0,%1,%2,%3}, [%4];"
        : "=r"(r[0]), "=r"(r[1]), "=r"(r[2]), "=r"(r[3]) : "r"(a));
}
__device__ __forceinline__ void ldm2(uint32_t* r, uint32_t a){
    asm volatile("ldmatrix.sync.aligned.m8n8.x2.shared.b16 {%0,%1}, [%2];"
        : "=r"(r[0]), "=r"(r[1]) : "r"(a));
}
__device__ __forceinline__ void mma16816(float* d, const uint32_t* a, const uint32_t* b){
    asm volatile("mma.sync.aligned.m16n8k16.row.col.f32.f16.f16.f32 "
        "{%0,%1,%2,%3}, {%4,%5,%6,%7}, {%8,%9}, {%0,%1,%2,%3};"
        : "+f"(d[0]), "+f"(d[1]), "+f"(d[2]), "+f"(d[3])
        : "r"(a[0]), "r"(a[1]), "r"(a[2]), "r"(a[3]), "r"(b[0]), "r"(b[1]));
}

// ---------------- generic mma.sync GEMM -------------------------------------
// C[128x128] per CTA; NT form: C[m,n] = sum_k A[m,k]*B[n,k], A/B fp16 hi/lo
// row-major. 3-term split. modes: 0 = fp16 hi/lo out + bias (Q/K proj),
// 1 = exp(scale*v) with causal mask -> fp32 (scores), 2 = plain fp32 (context),
// 3 = fp32 + bias (V proj).
#define BK    32
#define ROWH  40                   // fp16 elems per smem row (32 + 8 pad)
#define MATB  (128*ROWH*2)         // 10240 B per matrix tile
#define STAGEB (4*MATB)            // Ah, Al, Bh, Bl

__global__ void __launch_bounds__(256, 1) gemm16(
    const __half* __restrict__ Ah, const __half* __restrict__ Al,
    const __half* __restrict__ Bh, const __half* __restrict__ Bl,
    int ldA, int ldB, long long aZ, long long bZ,
    int mode, const float* __restrict__ bias,
    float* __restrict__ Of, __half* __restrict__ Oh, __half* __restrict__ Ol,
    long long oZ, int ldo, int nK, float scale)
{
    int bx = blockIdx.x, by = blockIdx.y, bz = blockIdx.z;
    if (mode == 1 && by > bx) return;            // fully-masked score tile
    if (mode == 2) nK = 4 * (by + 1);            // context: K truncated at diag

    extern __shared__ __align__(16) char smc[];
    uint32_t sb = smem_u32(smc);

    Ah += bz * aZ; Al += bz * aZ;
    Bh += bz * bZ; Bl += bz * bZ;

    int m0 = by * 128, n0 = bx * 128;
    int tid = threadIdx.x, lane = tid & 31, w = tid >> 5;
    int wm = w & 1, wn = w >> 1;                 // 2 x 4 warp grid (m x n)

    float acc[4][4][4];
    #pragma unroll
    for (int i = 0; i < 4; ++i)
        #pragma unroll
        for (int j = 0; j < 4; ++j)
            #pragma unroll
            for (int u = 0; u < 4; ++u) acc[i][j][u] = 0.f;

    int l15 = lane & 15;
    int aKsel = (lane >> 4) * 8;
    int bRow = l15 & 7, bKsel = (l15 >> 3) * 8;

#define LOADSTAGE(st, kb) {                                                    \
    int k0 = (kb) * BK;                                                        \
    uint32_t so_ = sb + (st) * STAGEB;                                         \
    _Pragma("unroll") for (int i = 0; i < 2; ++i) {                            \
        int c = tid + i * 256; int row = c >> 2, seg = c & 3;                  \
        uint32_t sd = so_ + row * 80 + seg * 16;                               \
        long long ga = (long long)(m0 + row) * ldA + k0 + seg * 8;             \
        long long gb = (long long)(n0 + row) * ldB + k0 + seg * 8;             \
        cp16(sd,            Ah + ga);                                          \
        cp16(sd + MATB,     Al + ga);                                          \
        cp16(sd + 2*MATB,   Bh + gb);                                          \
        cp16(sd + 3*MATB,   Bl + gb);                                          \
    }                                                                          \
    asm volatile("cp.async.commit_group;"); }

    LOADSTAGE(0, 0);
    if (nK > 1) LOADSTAGE(1, 1);

    for (int kb = 0; kb < nK; ++kb) {
        int st = kb & 1;
        if (kb + 1 < nK) asm volatile("cp.async.wait_group 1;");
        else             asm volatile("cp.async.wait_group 0;");
        __syncthreads();

        uint32_t so = sb + st * STAGEB;
        #pragma unroll
        for (int ks = 0; ks < 2; ++ks) {
            uint32_t ah[4][4], al[4][4], bh[4][2], bl[4][2];
            #pragma unroll
            for (int mi = 0; mi < 4; ++mi) {
                uint32_t off = ((wm*64 + mi*16 + l15) * ROWH + ks*16 + aKsel) * 2;
                ldm4(ah[mi], so + off);
                ldm4(al[mi], so + MATB + off);
            }
            #pragma unroll
            for (int ni = 0; ni < 4; ++ni) {
                uint32_t off = ((wn*32 + ni*8 + bRow) * ROWH + ks*16 + bKsel) * 2;
                ldm2(bh[ni], so + 2*MATB + off);
                ldm2(bl[ni], so + 3*MATB + off);
            }
            #pragma unroll
            for (int mi = 0; mi < 4; ++mi)
                #pragma unroll
                for (int ni = 0; ni < 4; ++ni) {
                    mma16816(acc[mi][ni], ah[mi], bh[ni]);
                    mma16816(acc[mi][ni], ah[mi], bl[ni]);
                    mma16816(acc[mi][ni], al[mi], bh[ni]);
                }
        }
        __syncthreads();
        if (kb + 2 < nK) LOADSTAGE(st, kb + 2);
    }

    // ---------------- epilogue ----------------
    #pragma unroll
    for (int mi = 0; mi < 4; ++mi)
        #pragma unroll
        for (int ni = 0; ni < 4; ++ni) {
            int r0 = m0 + wm*64 + mi*16 + (lane >> 2);
            int c  = n0 + wn*32 + ni*8 + (lane & 3) * 2;
            #pragma unroll
            for (int hr = 0; hr < 2; ++hr) {
                int r = r0 + hr * 8;
                float v0 = acc[mi][ni][hr*2 + 0];
                float v1 = acc[mi][ni][hr*2 + 1];
                if (mode == 0 || mode == 3) { v0 += __ldg(bias + c); v1 += __ldg(bias + c + 1); }
                if (mode == 1) {
                    v0 = (r <= c)     ? __expf(v0 * scale) : 0.f;
                    v1 = (r <= c + 1) ? __expf(v1 * scale) : 0.f;
                }
                if (mode == 0) {
                    __half h0 = __float2half(v0), h1 = __float2half(v1);
                    __half l0 = __float2half(v0 - __half2float(h0));
                    __half l1 = __float2half(v1 - __half2float(h1));
                    *(__half2*)(Oh + (long long)r * ldo + c) = __halves2half2(h0, h1);
                    *(__half2*)(Ol + (long long)r * ldo + c) = __halves2half2(l0, l1);
                } else {
                    *(float2*)(Of + (long long)bz * oZ + (long long)r * ldo + c)
                        = make_float2(v0, v1);
                }
            }
        }
}

// ---------------- elementwise fp32 -> fp16 hi/lo split ----------------------
__global__ void split_f32(const float* __restrict__ s, __half* __restrict__ h,
                          __half* __restrict__ l)
{
    long long i = ((long long)blockIdx.x * 256 + threadIdx.x) * 8;
    float4 a = *(const float4*)(s + i), b = *(const float4*)(s + i + 4);
    float v[8] = {a.x, a.y, a.z, a.w, b.x, b.y, b.z, b.w};
    union { uint4 u; __half e[8]; } H, L;
    #pragma unroll
    for (int j = 0; j < 8; ++j) {
        __half hh = __float2half(v[j]);
        H.e[j] = hh;
        L.e[j] = __float2half(v[j] - __half2float(hh));
    }
    *(uint4*)(h + i) = H.u;
    *(uint4*)(l + i) = L.u;
}

// ---------------- transpose + (optional) normalize + hi/lo split ------------
// src [R, ldS] fp32 (per z). Processes 64-row x 128-col chunk (kc, rt),
// writes dst[t][s] fp16 hi/lo with row length SEQ. If inv: multiply by
// inv[bz*SEQ + col] and write normalized value back to wb.
__global__ void pack_tr(const float* __restrict__ src, __half* __restrict__ dh,
                        __half* __restrict__ dl, int ldS, long long sZ, long long dZ,
                        const float* __restrict__ inv, float* __restrict__ wb, int causal)
{
    int kc = blockIdx.x, rt = blockIdx.y, bz = blockIdx.z;
    if (causal && kc * 64 > rt * 128 + 127) return;
    __shared__ float smt[64][129];
    const float* s = src + (long long)bz * sZ;
    int s0 = kc * 64, t0 = rt * 128;
    int tid = threadIdx.x;
    for (int i = 0; i < 32; ++i) {
        int idx = i * 256 + tid;
        int sr = idx >> 7, sc = idx & 127;
        float x = s[(long long)(s0 + sr) * ldS + t0 + sc];
        if (inv) {
            x *= inv[bz * SEQ + t0 + sc];
            wb[(long long)bz * sZ + (long long)(s0 + sr) * ldS + t0 + sc] = x;
        }
        smt[sr][sc] = x;
    }
    __syncthreads();
    int r = tid >> 1, half = tid & 1;
    long long db = (long long)bz * dZ + (long long)(t0 + r) * SEQ + s0 + half * 32;
    for (int g = 0; g < 4; ++g) {
        union { uint4 u; __half e[8]; } H, L;
        #pragma unroll
        for (int j = 0; j < 8; ++j) {
            float x = smt[half * 32 + g * 8 + j][r];
            __half hh = __float2half(x);
            H.e[j] = hh;
            L.e[j] = __float2half(x - __half2float(hh));
        }
        *(uint4*)(dh + db + g * 8) = H.u;
        *(uint4*)(dl + db + g * 8) = L.u;
    }
}

// ---------------- softmax denominators --------------------------------------
__global__ void colsum(const float* __restrict__ att, float* __restrict__ l)
{
    int t  = blockIdx.x * 256 + threadIdx.x;
    int b  = blockIdx.z;
    int s0 = blockIdx.y * 256;
    if (blockIdx.y > blockIdx.x) return;    // chunk fully masked (zeros)
    const float* p = att + (long long)b * SEQ * SEQ + (long long)s0 * SEQ + t;
    float a0 = 0.f, a1 = 0.f;
    for (int i = 0; i < 256; i += 2) {
        a0 += p[(long long)i * SEQ];
        a1 += p[(long long)(i + 1) * SEQ];
    }
    atomicAdd(&l[b * SEQ + t], a0 + a1);
}
__global__ void invert(float* __restrict__ l)
{
    int i = blockIdx.x * 256 + threadIdx.x;
    l[i] = 1.0f / l[i];
}

// ---------------- launch -----------------------------------------------------
extern "C" void kernel_launch(void* const* d_in, const int* in_sizes, int n_in,
                              void* d_out, int out_size)
{
    const float* X[3]  = {(const float*)d_in[0], (const float*)d_in[1], (const float*)d_in[2]};
    const float* W[3]  = {(const float*)d_in[3], (const float*)d_in[5], (const float*)d_in[7]};
    const float* Bv[3] = {(const float*)d_in[4], (const float*)d_in[6], (const float*)d_in[8]};
    float* out = (float*)d_out;

    cudaFuncSetAttribute(gemm16, cudaFuncAttributeMaxDynamicSharedMemorySize, 2 * STAGEB);

    __half *xh[3], *xl[3], *wh[3], *wl[3], *qh, *ql, *kh, *kl, *vth, *vtl, *ath, *atl;
    float *vf, *lsum, *attnScr;
    {   char* p;
        cudaGetSymbolAddress((void**)&p, g_xh); for (int i=0;i<3;++i) xh[i]=(__half*)p + (long long)i*RALL*HID;
        cudaGetSymbolAddress((void**)&p, g_xl); for (int i=0;i<3;++i) xl[i]=(__half*)p + (long long)i*RALL*HID;
        cudaGetSymbolAddress((void**)&p, g_wh); for (int i=0;i<3;++i) wh[i]=(__half*)p + (long long)i*HID*HID;
        cudaGetSymbolAddress((void**)&p, g_wl); for (int i=0;i<3;++i) wl[i]=(__half*)p + (long long)i*HID*HID;
        cudaGetSymbolAddress((void**)&qh, g_qh);  cudaGetSymbolAddress((void**)&ql, g_ql);
        cudaGetSymbolAddress((void**)&kh, g_kh);  cudaGetSymbolAddress((void**)&kl, g_kl);
        cudaGetSymbolAddress((void**)&vf, g_vf);
        cudaGetSymbolAddress((void**)&vth, g_vth); cudaGetSymbolAddress((void**)&vtl, g_vtl);
        cudaGetSymbolAddress((void**)&ath, g_ath); cudaGetSymbolAddress((void**)&atl, g_atl);
        cudaGetSymbolAddress((void**)&lsum, g_l);  cudaGetSymbolAddress((void**)&attnScr, g_attn);
    }

    const long long ctxElems  = (long long)BATCH * SEQ * HID;
    const long long attnElems = (long long)BATCH * SEQ * SEQ;
    float* ctx  = out;
    float* attn = ((long long)out_size >= ctxElems + attnElems) ? out + ctxElems : attnScr;

    const int dsz = 2 * STAGEB;
    const float scale = 0.03125f;   // 1/sqrt(1024)

    // 1) split inputs + weights to fp16 hi/lo
    for (int i = 0; i < 3; ++i) {
        split_f32<<<(RALL * HID) / 2048, 256>>>(X[i], xh[i], xl[i]);
        split_f32<<<(HID * HID) / 2048, 256>>>(W[i], wh[i], wl[i]);
    }
    // 2) projections (NT: A = X [m,k], B = W [n,k])
    gemm16<<<dim3(8, 64), 256, dsz>>>(xh[0], xl[0], wh[0], wl[0], HID, HID, 0, 0,
        0, Bv[0], nullptr, qh, ql, 0, HID, HID / BK, 1.f);
    gemm16<<<dim3(8, 64), 256, dsz>>>(xh[1], xl[1], wh[1], wl[1], HID, HID, 0, 0,
        0, Bv[1], nullptr, kh, kl, 0, HID, HID / BK, 1.f);
    gemm16<<<dim3(8, 64), 256, dsz>>>(xh[2], xl[2], wh[2], wl[2], HID, HID, 0, 0,
        3, Bv[2], vf, nullptr, nullptr, 0, HID, HID / BK, 1.f);
    // 3) V^T pack per batch: VT[b][h][s]
    pack_tr<<<dim3(32, 8, BATCH), 256>>>(vf, vth, vtl, HID,
        (long long)SEQ * HID, (long long)HID * SEQ, nullptr, nullptr, 0);
    // 4) scores: attn[b,s,t] = exp(scale * <K_s, Q_t>), causal-masked
    cudaMemsetAsync(attn, 0, attnElems * sizeof(float), 0);
    gemm16<<<dim3(16, 16, BATCH), 256, dsz>>>(kh, kl, qh, ql, HID, HID,
        (long long)SEQ * HID, (long long)SEQ * HID,
        1, nullptr, attn, nullptr, nullptr, (long long)SEQ * SEQ, SEQ, HID / BK, scale);
    // 5) softmax denominators over s
    cudaMemsetAsync(lsum, 0, BATCH * SEQ * sizeof(float), 0);
    colsum<<<dim3(8, 8, BATCH), 256>>>(attn, lsum);
    invert<<<BATCH * SEQ / 256, 256>>>(lsum);
    // 6) normalize attn in place + pack attn^T [b][t][s] hi/lo
    pack_tr<<<dim3(32, 16, BATCH), 256>>>(attn, ath, atl, SEQ,
        (long long)SEQ * SEQ, (long long)SEQ * SEQ, lsum, attn, 1);
    // 7) context: ctx[b,t,h] = sum_s AT[t,s] * VT[h,s]  (K truncated at diag)
    gemm16<<<dim3(8, 16, BATCH), 256, dsz>>>(ath, atl, vth, vtl, SEQ, SEQ,
        (long long)SEQ * SEQ, (long long)HID * SEQ,
        2, nullptr, ctx, nullptr, nullptr, (long long)SEQ * HID, HID, 0, 1.f);
}

// round 8
// speedup vs baseline: 2.4663x; 1.0331x over previous
#include <cuda_runtime.h>
#include <cuda_fp16.h>
#include <cstdint>

#define SEQ   2048
#define HID   1024
#define BATCH 4
#define RALL  (BATCH*SEQ)          // 8192

// ---------------- device scratch --------------------------------------------
__device__ __align__(16) __half g_xh[3][(long long)RALL*HID];
__device__ __align__(16) __half g_xl[3][(long long)RALL*HID];
__device__ __align__(16) __half g_wh[3][HID*HID];
__device__ __align__(16) __half g_wl[3][HID*HID];
__device__ __align__(16) __half g_qh[(long long)RALL*HID], g_ql[(long long)RALL*HID];
__device__ __align__(16) __half g_kh[(long long)RALL*HID], g_kl[(long long)RALL*HID];
__device__ float g_vf[(long long)RALL*HID];
__device__ __align__(16) __half g_vth[(long long)RALL*HID], g_vtl[(long long)RALL*HID];
__device__ __align__(16) __half g_ath[(long long)BATCH*SEQ*SEQ], g_atl[(long long)BATCH*SEQ*SEQ];
__device__ float g_attn[(long long)BATCH*SEQ*SEQ];
__device__ float g_l[BATCH*SEQ];

// ---------------- low-level helpers -----------------------------------------
__device__ __forceinline__ uint32_t smem_u32(const void* p){
    uint32_t a;
    asm("{ .reg .u64 t; cvta.to.shared.u64 t, %1; cvt.u32.u64 %0, t; }" : "=r"(a) : "l"(p));
    return a;
}
__device__ __forceinline__ void cp16(uint32_t d, const void* g){
    asm volatile("cp.async.cg.shared.global [%0], [%1], 16;" :: "r"(d), "l"(g));
}
__device__ __forceinline__ void ldm4(uint32_t* r, uint32_t a){
    asm volatile("ldmatrix.sync.aligned.m8n8.x4.shared.b16 {%0,%1,%2,%3}, [%4];"
        : "=r"(r[0]), "=r"(r[1]), "=r"(r[2]), "=r"(r[3]) : "r"(a));
}
__device__ __forceinline__ void mma16816(float* d, const uint32_t* a, const uint32_t* b){
    asm volatile("mma.sync.aligned.m16n8k16.row.col.f32.f16.f16.f32 "
        "{%0,%1,%2,%3}, {%4,%5,%6,%7}, {%8,%9}, {%0,%1,%2,%3};"
        : "+f"(d[0]), "+f"(d[1]), "+f"(d[2]), "+f"(d[3])
        : "r"(a[0]), "r"(a[1]), "r"(a[2]), "r"(a[3]), "r"(b[0]), "r"(b[1]));
}

#define BK     32
#define ROWH   40                  // fp16 elems per smem row (32 + 8 pad, 80B stride)
#define MATB   (128*ROWH*2)        // 10240 B per matrix tile
#define STAGEB (4*MATB)            // Ah, Al, Bh, Bl = 40960 B
#define NSTAGE 3
#define SMTOT  (NSTAGE*STAGEB)     // 122880 B

// ---------------- shared GEMM body ------------------------------------------
// C[128x128]; NT: C[m,n] = sum_k A[m,k]*B[n,k]; fp16 hi/lo, 3-term split.
// modes: 0 = fp16 hi/lo out + bias (Q/K proj), 1 = exp(scale*v) causal -> fp32
// + fused column sums, 2 = plain fp32 (context), 3 = fp32 + bias (V proj).
__device__ __forceinline__ void gemm_body(
    const __half* __restrict__ Ah, const __half* __restrict__ Al,
    const __half* __restrict__ Bh, const __half* __restrict__ Bl,
    int ldA, int ldB, int m0, int n0, int nK, int mode,
    const float* __restrict__ bias,
    float* __restrict__ Of, __half* __restrict__ Oh, __half* __restrict__ Ol,
    int ldo, float scale, float* __restrict__ lsum, char* smc)
{
    uint32_t sb = smem_u32(smc);
    int tid = threadIdx.x, lane = tid & 31, w = tid >> 5;
    int wm = w & 1, wn = w >> 1;                 // 2 x 4 warp grid (m x n)

    float acc[4][4][4];
    #pragma unroll
    for (int i = 0; i < 4; ++i)
        #pragma unroll
        for (int j = 0; j < 4; ++j)
            #pragma unroll
            for (int u = 0; u < 4; ++u) acc[i][j][u] = 0.f;

    int l15 = lane & 15;
    int aKsel = (lane >> 4) * 8;

#define LOADSTAGE(st, kb) {                                                    \
    int k0 = (kb) * BK;                                                        \
    uint32_t so_ = sb + (st) * STAGEB;                                         \
    _Pragma("unroll") for (int i = 0; i < 2; ++i) {                            \
        int c = tid + i * 256; int row = c >> 2, seg = c & 3;                  \
        uint32_t sd = so_ + row * 80 + seg * 16;                               \
        long long ga = (long long)(m0 + row) * ldA + k0 + seg * 8;             \
        long long gb = (long long)(n0 + row) * ldB + k0 + seg * 8;             \
        cp16(sd,            Ah + ga);                                          \
        cp16(sd + MATB,     Al + ga);                                          \
        cp16(sd + 2*MATB,   Bh + gb);                                          \
        cp16(sd + 3*MATB,   Bl + gb);                                          \
    }                                                                          \
    asm volatile("cp.async.commit_group;"); }

    LOADSTAGE(0, 0);
    if (nK > 1) LOADSTAGE(1, 1);
    if (nK > 2) LOADSTAGE(2, 2);

    for (int kb = 0; kb < nK; ++kb) {
        int st = kb % NSTAGE;
        int issued = (kb + 3 < nK) ? kb + 3 : nK;
        int pend = issued - kb - 1;
        if (pend >= 2)      asm volatile("cp.async.wait_group 2;");
        else if (pend == 1) asm volatile("cp.async.wait_group 1;");
        else                asm volatile("cp.async.wait_group 0;");
        __syncthreads();

        uint32_t so = sb + st * STAGEB;
        #pragma unroll
        for (int ks = 0; ks < 2; ++ks) {
            uint32_t ah[4][4], al[4][4], bh[4][2], bl[4][2];
            #pragma unroll
            for (int mi = 0; mi < 4; ++mi) {
                uint32_t off = ((wm*64 + mi*16 + l15) * ROWH + ks*16 + aKsel) * 2;
                ldm4(ah[mi], so + off);
                ldm4(al[mi], so + MATB + off);
            }
            #pragma unroll
            for (int np = 0; np < 2; ++np) {
                uint32_t off = ((wn*32 + np*16 + ((lane >> 4) << 3) + (lane & 7)) * ROWH
                                + ks*16 + ((lane >> 3) & 1) * 8) * 2;
                uint32_t t0[4], t1[4];
                ldm4(t0, so + 2*MATB + off);
                ldm4(t1, so + 3*MATB + off);
                bh[2*np][0] = t0[0]; bh[2*np][1] = t0[1];
                bh[2*np+1][0] = t0[2]; bh[2*np+1][1] = t0[3];
                bl[2*np][0] = t1[0]; bl[2*np][1] = t1[1];
                bl[2*np+1][0] = t1[2]; bl[2*np+1][1] = t1[3];
            }
            #pragma unroll
            for (int mi = 0; mi < 4; ++mi)
                #pragma unroll
                for (int ni = 0; ni < 4; ++ni) {
                    mma16816(acc[mi][ni], ah[mi], bh[ni]);
                    mma16816(acc[mi][ni], ah[mi], bl[ni]);
                    mma16816(acc[mi][ni], al[mi], bh[ni]);
                }
        }
        __syncthreads();
        if (kb + 3 < nK) LOADSTAGE(st, kb + 3);
    }
#undef LOADSTAGE

    // ---------------- epilogue ----------------
    float* cs = (float*)smc;             // per-CTA column sums (mode 1)
    if (mode == 1) {
        if (tid < 128) cs[tid] = 0.f;
        __syncthreads();
    }

    #pragma unroll
    for (int mi = 0; mi < 4; ++mi)
        #pragma unroll
        for (int ni = 0; ni < 4; ++ni) {
            int r0 = m0 + wm*64 + mi*16 + (lane >> 2);
            int cl = wn*32 + ni*8 + (lane & 3) * 2;     // col within tile
            int c  = n0 + cl;
            float s0 = 0.f, s1 = 0.f;
            #pragma unroll
            for (int hr = 0; hr < 2; ++hr) {
                int r = r0 + hr * 8;
                float v0 = acc[mi][ni][hr*2 + 0];
                float v1 = acc[mi][ni][hr*2 + 1];
                if (mode == 0 || mode == 3) { v0 += __ldg(bias + c); v1 += __ldg(bias + c + 1); }
                if (mode == 1) {
                    v0 = (r <= c)     ? __expf(v0 * scale) : 0.f;
                    v1 = (r <= c + 1) ? __expf(v1 * scale) : 0.f;
                    s0 += v0; s1 += v1;
                }
                if (mode == 0) {
                    __half h0 = __float2half(v0), h1 = __float2half(v1);
                    __half l0 = __float2half(v0 - __half2float(h0));
                    __half l1 = __float2half(v1 - __half2float(h1));
                    *(__half2*)(Oh + (long long)r * ldo + c) = __halves2half2(h0, h1);
                    *(__half2*)(Ol + (long long)r * ldo + c) = __halves2half2(l0, l1);
                } else {
                    *(float2*)(Of + (long long)r * ldo + c) = make_float2(v0, v1);
                }
            }
            if (mode == 1) { atomicAdd(&cs[cl], s0); atomicAdd(&cs[cl + 1], s1); }
        }

    if (mode == 1) {
        __syncthreads();
        if (tid < 128) atomicAdd(&lsum[n0 + tid], cs[tid]);
    }
}

// ---------------- wrappers ---------------------------------------------------
__global__ void __launch_bounds__(256, 1) gemm_z(
    const __half* __restrict__ Ah, const __half* __restrict__ Al,
    const __half* __restrict__ Bh, const __half* __restrict__ Bl,
    int ldA, int ldB, long long aZ, long long bZ, int mode,
    float* __restrict__ Of, long long oZ, int ldo, int nK, float scale,
    float* __restrict__ lsum)
{
    int bx = blockIdx.x, by = blockIdx.y, bz = blockIdx.z;
    if (mode == 1 && by > bx) return;            // fully-masked score tile
    if (mode == 2) nK = 4 * (by + 1);            // context: K truncated at diag
    extern __shared__ __align__(16) char smc[];
    gemm_body(Ah + bz*aZ, Al + bz*aZ, Bh + bz*bZ, Bl + bz*bZ, ldA, ldB,
              by*128, bx*128, nK, mode, nullptr,
              Of + (long long)bz*oZ, nullptr, nullptr, ldo, scale,
              lsum ? lsum + bz*SEQ : nullptr, smc);
}

struct ProjPtrs {
    const __half* ah[3]; const __half* al[3];
    const __half* bh[3]; const __half* bl[3];
    const float*  bias[3];
    __half* oh[3]; __half* ol[3]; float* of[3];
};

__global__ void __launch_bounds__(256, 1) gemm_proj(ProjPtrs P)
{
    int z = blockIdx.z;
    int mode = (z == 2) ? 3 : 0;
    extern __shared__ __align__(16) char smc[];
    gemm_body(P.ah[z], P.al[z], P.bh[z], P.bl[z], HID, HID,
              blockIdx.y*128, blockIdx.x*128, HID / BK, mode, P.bias[z],
              P.of[z], P.oh[z], P.ol[z], HID, 1.f, nullptr, smc);
}

// ---------------- fp32 -> fp16 hi/lo split (3 sources) ----------------------
__global__ void split3(const float* __restrict__ s0, const float* __restrict__ s1,
                       const float* __restrict__ s2, __half* __restrict__ h,
                       __half* __restrict__ l, long long perZ)
{
    int z = blockIdx.y;
    const float* s = (z == 0) ? s0 : ((z == 1) ? s1 : s2);
    long long i = ((long long)blockIdx.x * 256 + threadIdx.x) * 8;
    float4 a = *(const float4*)(s + i), b = *(const float4*)(s + i + 4);
    float v[8] = {a.x, a.y, a.z, a.w, b.x, b.y, b.z, b.w};
    union { uint4 u; __half e[8]; } H, L;
    #pragma unroll
    for (int j = 0; j < 8; ++j) {
        __half hh = __float2half(v[j]);
        H.e[j] = hh;
        L.e[j] = __float2half(v[j] - __half2float(hh));
    }
    *(uint4*)(h + z * perZ + i) = H.u;
    *(uint4*)(l + z * perZ + i) = L.u;
}

// ---------------- transpose + (optional) normalize + hi/lo split ------------
__global__ void pack_tr(const float* __restrict__ src, __half* __restrict__ dh,
                        __half* __restrict__ dl, int ldS, long long sZ, long long dZ,
                        const float* __restrict__ inv, float* __restrict__ wb, int causal)
{
    int kc = blockIdx.x, rt = blockIdx.y, bz = blockIdx.z;
    if (causal && kc * 64 > rt * 128 + 127) return;
    __shared__ float smt[64][129];
    const float* s = src + (long long)bz * sZ;
    int s0 = kc * 64, t0 = rt * 128;
    int tid = threadIdx.x;
    for (int i = 0; i < 32; ++i) {
        int idx = i * 256 + tid;
        int sr = idx >> 7, sc = idx & 127;
        float x = s[(long long)(s0 + sr) * ldS + t0 + sc];
        if (inv) {
            x *= inv[bz * SEQ + t0 + sc];
            wb[(long long)bz * sZ + (long long)(s0 + sr) * ldS + t0 + sc] = x;
        }
        smt[sr][sc] = x;
    }
    __syncthreads();
    int r = tid >> 1, half = tid & 1;
    long long db = (long long)bz * dZ + (long long)(t0 + r) * SEQ + s0 + half * 32;
    for (int g = 0; g < 4; ++g) {
        union { uint4 u; __half e[8]; } H, L;
        #pragma unroll
        for (int j = 0; j < 8; ++j) {
            float x = smt[half * 32 + g * 8 + j][r];
            __half hh = __float2half(x);
            H.e[j] = hh;
            L.e[j] = __float2half(x - __half2float(hh));
        }
        *(uint4*)(dh + db + g * 8) = H.u;
        *(uint4*)(dl + db + g * 8) = L.u;
    }
}

__global__ void invert(float* __restrict__ l)
{
    int i = blockIdx.x * 256 + threadIdx.x;
    l[i] = 1.0f / l[i];
}

// ---------------- launch -----------------------------------------------------
extern "C" void kernel_launch(void* const* d_in, const int* in_sizes, int n_in,
                              void* d_out, int out_size)
{
    const float* X[3]  = {(const float*)d_in[0], (const float*)d_in[1], (const float*)d_in[2]};
    const float* W[3]  = {(const float*)d_in[3], (const float*)d_in[5], (const float*)d_in[7]};
    const float* Bv[3] = {(const float*)d_in[4], (const float*)d_in[6], (const float*)d_in[8]};
    float* out = (float*)d_out;

    cudaFuncSetAttribute(gemm_z,    cudaFuncAttributeMaxDynamicSharedMemorySize, SMTOT);
    cudaFuncSetAttribute(gemm_proj, cudaFuncAttributeMaxDynamicSharedMemorySize, SMTOT);

    __half *xh, *xl, *wh, *wl, *qh, *ql, *kh, *kl, *vth, *vtl, *ath, *atl;
    float *vf, *lsum, *attnScr;
    cudaGetSymbolAddress((void**)&xh, g_xh);   cudaGetSymbolAddress((void**)&xl, g_xl);
    cudaGetSymbolAddress((void**)&wh, g_wh);   cudaGetSymbolAddress((void**)&wl, g_wl);
    cudaGetSymbolAddress((void**)&qh, g_qh);   cudaGetSymbolAddress((void**)&ql, g_ql);
    cudaGetSymbolAddress((void**)&kh, g_kh);   cudaGetSymbolAddress((void**)&kl, g_kl);
    cudaGetSymbolAddress((void**)&vf, g_vf);
    cudaGetSymbolAddress((void**)&vth, g_vth); cudaGetSymbolAddress((void**)&vtl, g_vtl);
    cudaGetSymbolAddress((void**)&ath, g_ath); cudaGetSymbolAddress((void**)&atl, g_atl);
    cudaGetSymbolAddress((void**)&lsum, g_l);  cudaGetSymbolAddress((void**)&attnScr, g_attn);

    const long long ctxElems  = (long long)BATCH * SEQ * HID;
    const long long attnElems = (long long)BATCH * SEQ * SEQ;
    float* ctx  = out;
    float* attn = ((long long)out_size >= ctxElems + attnElems) ? out + ctxElems : attnScr;

    const long long XPZ = (long long)RALL * HID, WPZ = (long long)HID * HID;
    const float scale = 0.03125f;   // 1/sqrt(1024)

    // 1) split inputs + weights to fp16 hi/lo (one launch each)
    split3<<<dim3((unsigned)(XPZ / 2048), 3), 256>>>(X[0], X[1], X[2], xh, xl, XPZ);
    split3<<<dim3((unsigned)(WPZ / 2048), 3), 256>>>(W[0], W[1], W[2], wh, wl, WPZ);

    // 2) all three projections in one launch (z = 0:Q, 1:K, 2:V)
    ProjPtrs P;
    for (int i = 0; i < 3; ++i) {
        P.ah[i] = xh + i * XPZ; P.al[i] = xl + i * XPZ;
        P.bh[i] = wh + i * WPZ; P.bl[i] = wl + i * WPZ;
        P.bias[i] = Bv[i];
        P.oh[i] = nullptr; P.ol[i] = nullptr; P.of[i] = nullptr;
    }
    P.oh[0] = qh; P.ol[0] = ql;
    P.oh[1] = kh; P.ol[1] = kl;
    P.of[2] = vf;
    gemm_proj<<<dim3(8, 64, 3), 256, SMTOT>>>(P);

    // 3) V^T pack per batch: VT[b][h][s]
    pack_tr<<<dim3(32, 8, BATCH), 256>>>(vf, vth, vtl, HID,
        (long long)SEQ * HID, (long long)HID * SEQ, nullptr, nullptr, 0);

    // 4) scores: attn[b,s,t] = exp(scale * <K_s, Q_t>), causal; fused colsum
    cudaMemsetAsync(attn, 0, attnElems * sizeof(float), 0);
    cudaMemsetAsync(lsum, 0, BATCH * SEQ * sizeof(float), 0);
    gemm_z<<<dim3(16, 16, BATCH), 256, SMTOT>>>(kh, kl, qh, ql, HID, HID,
        (long long)SEQ * HID, (long long)SEQ * HID,
        1, attn, (long long)SEQ * SEQ, SEQ, HID / BK, scale, lsum);
    invert<<<BATCH * SEQ / 256, 256>>>(lsum);

    // 5) normalize attn in place + pack attn^T [b][t][s] hi/lo
    pack_tr<<<dim3(32, 16, BATCH), 256>>>(attn, ath, atl, SEQ,
        (long long)SEQ * SEQ, (long long)SEQ * SEQ, lsum, attn, 1);

    // 6) context: ctx[b,t,h] = sum_s AT[t,s] * VT[h,s]  (K truncated at diag)
    gemm_z<<<dim3(8, 16, BATCH), 256, SMTOT>>>(ath, atl, vth, vtl, SEQ, SEQ,
        (long long)SEQ * SEQ, (long long)HID * SEQ,
        2, ctx, (long long)SEQ * HID, HID, 0, 1.f, nullptr);
}

// round 9
// speedup vs baseline: 2.8439x; 1.1531x over previous
#include <cuda_runtime.h>
#include <cuda_fp16.h>
#include <cstdint>

#define SEQ   2048
#define HID   1024
#define BATCH 4
#define RALL  (BATCH*SEQ)          // 8192

// ---------------- device scratch --------------------------------------------
__device__ __align__(16) __half g_xh[3][(long long)RALL*HID];
__device__ __align__(16) __half g_xl[3][(long long)RALL*HID];
__device__ __align__(16) __half g_wh[3][HID*HID];
__device__ __align__(16) __half g_wl[3][HID*HID];
__device__ __align__(16) __half g_qh[(long long)RALL*HID], g_ql[(long long)RALL*HID];
__device__ __align__(16) __half g_kh[(long long)RALL*HID], g_kl[(long long)RALL*HID];
__device__ float g_vf[(long long)RALL*HID];
__device__ __align__(16) __half g_vth[(long long)RALL*HID], g_vtl[(long long)RALL*HID];
__device__ __align__(16) __half g_ath[(long long)BATCH*SEQ*SEQ], g_atl[(long long)BATCH*SEQ*SEQ];
__device__ float g_attn[(long long)BATCH*SEQ*SEQ];
__device__ float g_l[BATCH*SEQ];

// ---------------- low-level helpers -----------------------------------------
__device__ __forceinline__ uint32_t smem_u32(const void* p){
    uint32_t a;
    asm("{ .reg .u64 t; cvta.to.shared.u64 t, %1; cvt.u32.u64 %0, t; }" : "=r"(a) : "l"(p));
    return a;
}
__device__ __forceinline__ void cp16(uint32_t d, const void* g){
    asm volatile("cp.async.cg.shared.global [%0], [%1], 16;" :: "r"(d), "l"(g));
}
__device__ __forceinline__ void ldm4(uint32_t* r, uint32_t a){
    asm volatile("ldmatrix.sync.aligned.m8n8.x4.shared.b16 {%0,%1,%2,%3}, [%4];"
        : "=r"(r[0]), "=r"(r[1]), "=r"(r[2]), "=r"(r[3]) : "r"(a));
}
__device__ __forceinline__ void mma16816(float* d, const uint32_t* a, const uint32_t* b){
    asm volatile("mma.sync.aligned.m16n8k16.row.col.f32.f16.f16.f32 "
        "{%0,%1,%2,%3}, {%4,%5,%6,%7}, {%8,%9}, {%0,%1,%2,%3};"
        : "+f"(d[0]), "+f"(d[1]), "+f"(d[2]), "+f"(d[3])
        : "r"(a[0]), "r"(a[1]), "r"(a[2]), "r"(a[3]), "r"(b[0]), "r"(b[1]));
}

#define BK     32
#define ROWH   40                  // fp16 elems per smem row (32 + 8 pad, 80B stride)
#define MATB   (128*ROWH*2)        // 10240 B per matrix tile
#define STAGEB (4*MATB)            // Ah, Al, Bh, Bl = 40960 B
#define NSTAGE 2
#define SMTOT  (NSTAGE*STAGEB)     // 81920 B  -> 2 CTAs/SM

// ---------------- shared GEMM body ------------------------------------------
// C[128x128]; NT: C[m,n] = sum_k A[m,k]*B[n,k]; fp16 hi/lo, 3-term split.
// modes: 0 = fp16 hi/lo out + bias (Q/K proj), 1 = exp(scale*v) causal -> fp32
// + fused column sums, 2 = plain fp32 (context), 3 = fp32 + bias (V proj).
__device__ __forceinline__ void gemm_body(
    const __half* __restrict__ Ah, const __half* __restrict__ Al,
    const __half* __restrict__ Bh, const __half* __restrict__ Bl,
    int ldA, int ldB, int m0, int n0, int nK, int mode,
    const float* __restrict__ bias,
    float* __restrict__ Of, __half* __restrict__ Oh, __half* __restrict__ Ol,
    int ldo, float scale, float* __restrict__ lsum, char* smc)
{
    uint32_t sb = smem_u32(smc);
    int tid = threadIdx.x, lane = tid & 31, w = tid >> 5;
    int wm = w & 1, wn = w >> 1;                 // 2 x 4 warp grid (m x n)

    float acc[4][4][4];
    #pragma unroll
    for (int i = 0; i < 4; ++i)
        #pragma unroll
        for (int j = 0; j < 4; ++j)
            #pragma unroll
            for (int u = 0; u < 4; ++u) acc[i][j][u] = 0.f;

    int l15 = lane & 15;
    int aKsel = (lane >> 4) * 8;

#define LOADSTAGE(st, kb) {                                                    \
    int k0 = (kb) * BK;                                                        \
    uint32_t so_ = sb + (st) * STAGEB;                                         \
    _Pragma("unroll") for (int i = 0; i < 2; ++i) {                            \
        int c = tid + i * 256; int row = c >> 2, seg = c & 3;                  \
        uint32_t sd = so_ + row * 80 + seg * 16;                               \
        long long ga = (long long)(m0 + row) * ldA + k0 + seg * 8;             \
        long long gb = (long long)(n0 + row) * ldB + k0 + seg * 8;             \
        cp16(sd,            Ah + ga);                                          \
        cp16(sd + MATB,     Al + ga);                                          \
        cp16(sd + 2*MATB,   Bh + gb);                                          \
        cp16(sd + 3*MATB,   Bl + gb);                                          \
    }                                                                          \
    asm volatile("cp.async.commit_group;"); }

    LOADSTAGE(0, 0);
    if (nK > 1) LOADSTAGE(1, 1);

    for (int kb = 0; kb < nK; ++kb) {
        int st = kb & 1;
        if (kb + 1 < nK) asm volatile("cp.async.wait_group 1;");
        else             asm volatile("cp.async.wait_group 0;");
        __syncthreads();

        uint32_t so = sb + st * STAGEB;
        #pragma unroll
        for (int ks = 0; ks < 2; ++ks) {
            uint32_t ah[4][4], al[4][4], bh[4][2], bl[4][2];
            #pragma unroll
            for (int mi = 0; mi < 4; ++mi) {
                uint32_t off = ((wm*64 + mi*16 + l15) * ROWH + ks*16 + aKsel) * 2;
                ldm4(ah[mi], so + off);
                ldm4(al[mi], so + MATB + off);
            }
            #pragma unroll
            for (int np = 0; np < 2; ++np) {
                uint32_t off = ((wn*32 + np*16 + ((lane >> 4) << 3) + (lane & 7)) * ROWH
                                + ks*16 + ((lane >> 3) & 1) * 8) * 2;
                uint32_t t0[4], t1[4];
                ldm4(t0, so + 2*MATB + off);
                ldm4(t1, so + 3*MATB + off);
                bh[2*np][0] = t0[0]; bh[2*np][1] = t0[1];
                bh[2*np+1][0] = t0[2]; bh[2*np+1][1] = t0[3];
                bl[2*np][0] = t1[0]; bl[2*np][1] = t1[1];
                bl[2*np+1][0] = t1[2]; bl[2*np+1][1] = t1[3];
            }
            #pragma unroll
            for (int mi = 0; mi < 4; ++mi)
                #pragma unroll
                for (int ni = 0; ni < 4; ++ni) {
                    mma16816(acc[mi][ni], ah[mi], bh[ni]);
                    mma16816(acc[mi][ni], ah[mi], bl[ni]);
                    mma16816(acc[mi][ni], al[mi], bh[ni]);
                }
        }
        __syncthreads();
        if (kb + 2 < nK) LOADSTAGE(st, kb + 2);
    }
#undef LOADSTAGE

    // ---------------- epilogue ----------------
    float* cs = (float*)smc;             // per-CTA column sums (mode 1)
    if (mode == 1) {
        if (tid < 128) cs[tid] = 0.f;
        __syncthreads();
    }

    #pragma unroll
    for (int mi = 0; mi < 4; ++mi)
        #pragma unroll
        for (int ni = 0; ni < 4; ++ni) {
            int r0 = m0 + wm*64 + mi*16 + (lane >> 2);
            int cl = wn*32 + ni*8 + (lane & 3) * 2;     // col within tile
            int c  = n0 + cl;
            float s0 = 0.f, s1 = 0.f;
            #pragma unroll
            for (int hr = 0; hr < 2; ++hr) {
                int r = r0 + hr * 8;
                float v0 = acc[mi][ni][hr*2 + 0];
                float v1 = acc[mi][ni][hr*2 + 1];
                if (mode == 0 || mode == 3) { v0 += __ldg(bias + c); v1 += __ldg(bias + c + 1); }
                if (mode == 1) {
                    v0 = (r <= c)     ? __expf(v0 * scale) : 0.f;
                    v1 = (r <= c + 1) ? __expf(v1 * scale) : 0.f;
                    s0 += v0; s1 += v1;
                }
                if (mode == 0) {
                    __half h0 = __float2half(v0), h1 = __float2half(v1);
                    __half l0 = __float2half(v0 - __half2float(h0));
                    __half l1 = __float2half(v1 - __half2float(h1));
                    *(__half2*)(Oh + (long long)r * ldo + c) = __halves2half2(h0, h1);
                    *(__half2*)(Ol + (long long)r * ldo + c) = __halves2half2(l0, l1);
                } else {
                    *(float2*)(Of + (long long)r * ldo + c) = make_float2(v0, v1);
                }
            }
            if (mode == 1) { atomicAdd(&cs[cl], s0); atomicAdd(&cs[cl + 1], s1); }
        }

    if (mode == 1) {
        __syncthreads();
        if (tid < 128) atomicAdd(&lsum[n0 + tid], cs[tid]);
    }
}

// ---------------- wrappers ---------------------------------------------------
__global__ void __launch_bounds__(256, 2) gemm_z(
    const __half* __restrict__ Ah, const __half* __restrict__ Al,
    const __half* __restrict__ Bh, const __half* __restrict__ Bl,
    int ldA, int ldB, long long aZ, long long bZ, int mode,
    float* __restrict__ Of, long long oZ, int ldo, int nK, float scale,
    float* __restrict__ lsum)
{
    int bx = blockIdx.x, by = blockIdx.y, bz = blockIdx.z;
    if (mode == 1 && by > bx) return;            // fully-masked score tile
    if (mode == 2) nK = 4 * (by + 1);            // context: K truncated at diag
    extern __shared__ __align__(16) char smc[];
    gemm_body(Ah + bz*aZ, Al + bz*aZ, Bh + bz*bZ, Bl + bz*bZ, ldA, ldB,
              by*128, bx*128, nK, mode, nullptr,
              Of + (long long)bz*oZ, nullptr, nullptr, ldo, scale,
              lsum ? lsum + bz*SEQ : nullptr, smc);
}

struct ProjPtrs {
    const __half* ah[3]; const __half* al[3];
    const __half* bh[3]; const __half* bl[3];
    const float*  bias[3];
    __half* oh[3]; __half* ol[3]; float* of[3];
};

__global__ void __launch_bounds__(256, 2) gemm_proj(ProjPtrs P)
{
    int z = blockIdx.z;
    int mode = (z == 2) ? 3 : 0;
    extern __shared__ __align__(16) char smc[];
    gemm_body(P.ah[z], P.al[z], P.bh[z], P.bl[z], HID, HID,
              blockIdx.y*128, blockIdx.x*128, HID / BK, mode, P.bias[z],
              P.of[z], P.oh[z], P.ol[z], HID, 1.f, nullptr, smc);
}

// ---------------- fp32 -> fp16 hi/lo split (3 sources) ----------------------
__global__ void split3(const float* __restrict__ s0, const float* __restrict__ s1,
                       const float* __restrict__ s2, __half* __restrict__ h,
                       __half* __restrict__ l, long long perZ)
{
    int z = blockIdx.y;
    const float* s = (z == 0) ? s0 : ((z == 1) ? s1 : s2);
    long long i = ((long long)blockIdx.x * 256 + threadIdx.x) * 8;
    float4 a = *(const float4*)(s + i), b = *(const float4*)(s + i + 4);
    float v[8] = {a.x, a.y, a.z, a.w, b.x, b.y, b.z, b.w};
    union { uint4 u; __half e[8]; } H, L;
    #pragma unroll
    for (int j = 0; j < 8; ++j) {
        __half hh = __float2half(v[j]);
        H.e[j] = hh;
        L.e[j] = __float2half(v[j] - __half2float(hh));
    }
    *(uint4*)(h + z * perZ + i) = H.u;
    *(uint4*)(l + z * perZ + i) = L.u;
}

// ---------------- transpose + (optional) normalize + hi/lo split ------------
__global__ void pack_tr(const float* __restrict__ src, __half* __restrict__ dh,
                        __half* __restrict__ dl, int ldS, long long sZ, long long dZ,
                        const float* __restrict__ inv, float* __restrict__ wb, int causal)
{
    int kc = blockIdx.x, rt = blockIdx.y, bz = blockIdx.z;
    if (causal && kc * 64 > rt * 128 + 127) return;
    __shared__ float smt[64][129];
    const float* s = src + (long long)bz * sZ;
    int s0 = kc * 64, t0 = rt * 128;
    int tid = threadIdx.x;
    for (int i = 0; i < 32; ++i) {
        int idx = i * 256 + tid;
        int sr = idx >> 7, sc = idx & 127;
        float x = s[(long long)(s0 + sr) * ldS + t0 + sc];
        if (inv) {
            x *= inv[bz * SEQ + t0 + sc];
            wb[(long long)bz * sZ + (long long)(s0 + sr) * ldS + t0 + sc] = x;
        }
        smt[sr][sc] = x;
    }
    __syncthreads();
    int r = tid >> 1, half = tid & 1;
    long long db = (long long)bz * dZ + (long long)(t0 + r) * SEQ + s0 + half * 32;
    for (int g = 0; g < 4; ++g) {
        union { uint4 u; __half e[8]; } H, L;
        #pragma unroll
        for (int j = 0; j < 8; ++j) {
            float x = smt[half * 32 + g * 8 + j][r];
            __half hh = __float2half(x);
            H.e[j] = hh;
            L.e[j] = __float2half(x - __half2float(hh));
        }
        *(uint4*)(dh + db + g * 8) = H.u;
        *(uint4*)(dl + db + g * 8) = L.u;
    }
}

__global__ void invert(float* __restrict__ l)
{
    int i = blockIdx.x * 256 + threadIdx.x;
    l[i] = 1.0f / l[i];
}

// ---------------- launch -----------------------------------------------------
extern "C" void kernel_launch(void* const* d_in, const int* in_sizes, int n_in,
                              void* d_out, int out_size)
{
    const float* X[3]  = {(const float*)d_in[0], (const float*)d_in[1], (const float*)d_in[2]};
    const float* W[3]  = {(const float*)d_in[3], (const float*)d_in[5], (const float*)d_in[7]};
    const float* Bv[3] = {(const float*)d_in[4], (const float*)d_in[6], (const float*)d_in[8]};
    float* out = (float*)d_out;

    cudaFuncSetAttribute(gemm_z,    cudaFuncAttributeMaxDynamicSharedMemorySize, SMTOT);
    cudaFuncSetAttribute(gemm_proj, cudaFuncAttributeMaxDynamicSharedMemorySize, SMTOT);

    __half *xh, *xl, *wh, *wl, *qh, *ql, *kh, *kl, *vth, *vtl, *ath, *atl;
    float *vf, *lsum, *attnScr;
    cudaGetSymbolAddress((void**)&xh, g_xh);   cudaGetSymbolAddress((void**)&xl, g_xl);
    cudaGetSymbolAddress((void**)&wh, g_wh);   cudaGetSymbolAddress((void**)&wl, g_wl);
    cudaGetSymbolAddress((void**)&qh, g_qh);   cudaGetSymbolAddress((void**)&ql, g_ql);
    cudaGetSymbolAddress((void**)&kh, g_kh);   cudaGetSymbolAddress((void**)&kl, g_kl);
    cudaGetSymbolAddress((void**)&vf, g_vf);
    cudaGetSymbolAddress((void**)&vth, g_vth); cudaGetSymbolAddress((void**)&vtl, g_vtl);
    cudaGetSymbolAddress((void**)&ath, g_ath); cudaGetSymbolAddress((void**)&atl, g_atl);
    cudaGetSymbolAddress((void**)&lsum, g_l);  cudaGetSymbolAddress((void**)&attnScr, g_attn);

    const long long ctxElems  = (long long)BATCH * SEQ * HID;
    const long long attnElems = (long long)BATCH * SEQ * SEQ;
    float* ctx  = out;
    float* attn = ((long long)out_size >= ctxElems + attnElems) ? out + ctxElems : attnScr;

    const long long XPZ = (long long)RALL * HID, WPZ = (long long)HID * HID;
    const float scale = 0.03125f;   // 1/sqrt(1024)

    // 1) split inputs + weights to fp16 hi/lo (one launch each)
    split3<<<dim3((unsigned)(XPZ / 2048), 3), 256>>>(X[0], X[1], X[2], xh, xl, XPZ);
    split3<<<dim3((unsigned)(WPZ / 2048), 3), 256>>>(W[0], W[1], W[2], wh, wl, WPZ);

    // 2) all three projections in one launch (z = 0:Q, 1:K, 2:V)
    ProjPtrs P;
    for (int i = 0; i < 3; ++i) {
        P.ah[i] = xh + i * XPZ; P.al[i] = xl + i * XPZ;
        P.bh[i] = wh + i * WPZ; P.bl[i] = wl + i * WPZ;
        P.bias[i] = Bv[i];
        P.oh[i] = nullptr; P.ol[i] = nullptr; P.of[i] = nullptr;
    }
    P.oh[0] = qh; P.ol[0] = ql;
    P.oh[1] = kh; P.ol[1] = kl;
    P.of[2] = vf;
    gemm_proj<<<dim3(8, 64, 3), 256, SMTOT>>>(P);

    // 3) V^T pack per batch: VT[b][h][s]
    pack_tr<<<dim3(32, 8, BATCH), 256>>>(vf, vth, vtl, HID,
        (long long)SEQ * HID, (long long)HID * SEQ, nullptr, nullptr, 0);

    // 4) scores: attn[b,s,t] = exp(scale * <K_s, Q_t>), causal; fused colsum
    cudaMemsetAsync(attn, 0, attnElems * sizeof(float), 0);
    cudaMemsetAsync(lsum, 0, BATCH * SEQ * sizeof(float), 0);
    gemm_z<<<dim3(16, 16, BATCH), 256, SMTOT>>>(kh, kl, qh, ql, HID, HID,
        (long long)SEQ * HID, (long long)SEQ * HID,
        1, attn, (long long)SEQ * SEQ, SEQ, HID / BK, scale, lsum);
    invert<<<BATCH * SEQ / 256, 256>>>(lsum);

    // 5) normalize attn in place + pack attn^T [b][t][s] hi/lo
    pack_tr<<<dim3(32, 16, BATCH), 256>>>(attn, ath, atl, SEQ,
        (long long)SEQ * SEQ, (long long)SEQ * SEQ, lsum, attn, 1);

    // 6) context: ctx[b,t,h] = sum_s AT[t,s] * VT[h,s]  (K truncated at diag)
    gemm_z<<<dim3(8, 16, BATCH), 256, SMTOT>>>(ath, atl, vth, vtl, SEQ, SEQ,
        (long long)SEQ * SEQ, (long long)HID * SEQ,
        2, ctx, (long long)SEQ * HID, HID, 0, 1.f, nullptr);
}

// round 10
// speedup vs baseline: 3.3473x; 1.1770x over previous
#include <cuda_runtime.h>
#include <cuda_fp16.h>
#include <cstdint>

#define SEQ   2048
#define HID   1024
#define BATCH 4
#define RALL  (BATCH*SEQ)          // 8192

// ---------------- device scratch --------------------------------------------
__device__ __align__(16) __half g_xh[3][(long long)RALL*HID];
__device__ __align__(16) __half g_xl[3][(long long)RALL*HID];
__device__ __align__(16) __half g_wh[3][HID*HID];
__device__ __align__(16) __half g_wl[3][HID*HID];
__device__ __align__(16) __half g_qh[(long long)RALL*HID], g_ql[(long long)RALL*HID];
__device__ __align__(16) __half g_kh[(long long)RALL*HID], g_kl[(long long)RALL*HID];
__device__ float g_vf[(long long)RALL*HID];
__device__ __align__(16) __half g_vth[(long long)RALL*HID], g_vtl[(long long)RALL*HID];
__device__ __align__(16) __half g_ath[(long long)BATCH*SEQ*SEQ];
__device__ float g_attn[(long long)BATCH*SEQ*SEQ];
__device__ float g_l[BATCH*SEQ];

// ---------------- low-level helpers -----------------------------------------
__device__ __forceinline__ uint32_t smem_u32(const void* p){
    uint32_t a;
    asm("{ .reg .u64 t; cvta.to.shared.u64 t, %1; cvt.u32.u64 %0, t; }" : "=r"(a) : "l"(p));
    return a;
}
__device__ __forceinline__ void cp16(uint32_t d, const void* g){
    asm volatile("cp.async.cg.shared.global [%0], [%1], 16;" :: "r"(d), "l"(g));
}
__device__ __forceinline__ void ldm4(uint32_t* r, uint32_t a){
    asm volatile("ldmatrix.sync.aligned.m8n8.x4.shared.b16 {%0,%1,%2,%3}, [%4];"
        : "=r"(r[0]), "=r"(r[1]), "=r"(r[2]), "=r"(r[3]) : "r"(a));
}
__device__ __forceinline__ void mma16816(float* d, const uint32_t* a, const uint32_t* b){
    asm volatile("mma.sync.aligned.m16n8k16.row.col.f32.f16.f16.f32 "
        "{%0,%1,%2,%3}, {%4,%5,%6,%7}, {%8,%9}, {%0,%1,%2,%3};"
        : "+f"(d[0]), "+f"(d[1]), "+f"(d[2]), "+f"(d[3])
        : "r"(a[0]), "r"(a[1]), "r"(a[2]), "r"(a[3]), "r"(b[0]), "r"(b[1]));
}

#define BK     32
#define ROWH   40                  // fp16 elems per smem row (32 + 8 pad, 80B stride)
#define MATB   (128*ROWH*2)        // 10240 B per matrix tile
#define STAGEB (4*MATB)            // Ah, Al, Bh, Bl slots = 40960 B
#define NSTAGE 2
#define SMTOT  (NSTAGE*STAGEB)     // 81920 B -> 2 CTAs/SM

// ---------------- shared GEMM body ------------------------------------------
// C[128x128]; NT: C[m,n] = sum_k A[m,k]*B[n,k]; fp16 hi/lo split.
// TERMS=3: ah*bh + ah*bl + al*bh;  TERMS=2: ah*bh + ah*bl (A-lo never loaded).
// MODE: 0 = fp16 hi/lo out + bias, 1 = exp(scale*v) causal -> fp32 + colsum,
//       2 = fp32 out (optionally atomicAdd), 3 = fp32 + bias.
template<int MODE, int TERMS>
__device__ __forceinline__ void gemm_body(
    const __half* __restrict__ Ah, const __half* __restrict__ Al,
    const __half* __restrict__ Bh, const __half* __restrict__ Bl,
    int ldA, int ldB, int m0, int n0, int kStart, int nK,
    const float* __restrict__ bias,
    float* __restrict__ Of, __half* __restrict__ Oh, __half* __restrict__ Ol,
    int ldo, float scale, float* __restrict__ lsum, int atomicOut, char* smc)
{
    uint32_t sb = smem_u32(smc);
    int tid = threadIdx.x, lane = tid & 31, w = tid >> 5;
    int wm = w & 1, wn = w >> 1;                 // 2 x 4 warp grid (m x n)

    float acc[4][4][4];
    #pragma unroll
    for (int i = 0; i < 4; ++i)
        #pragma unroll
        for (int j = 0; j < 4; ++j)
            #pragma unroll
            for (int u = 0; u < 4; ++u) acc[i][j][u] = 0.f;

    int l15 = lane & 15;
    int aKsel = (lane >> 4) * 8;

#define LOADSTAGE(st, kb) {                                                    \
    int k0 = (kStart + (kb)) * BK;                                             \
    uint32_t so_ = sb + (st) * STAGEB;                                         \
    _Pragma("unroll") for (int i = 0; i < 2; ++i) {                            \
        int c = tid + i * 256; int row = c >> 2, seg = c & 3;                  \
        uint32_t sd = so_ + row * 80 + seg * 16;                               \
        long long ga = (long long)(m0 + row) * ldA + k0 + seg * 8;             \
        long long gb = (long long)(n0 + row) * ldB + k0 + seg * 8;             \
        cp16(sd,            Ah + ga);                                          \
        if (TERMS == 3) cp16(sd + MATB, Al + ga);                              \
        cp16(sd + 2*MATB,   Bh + gb);                                          \
        cp16(sd + 3*MATB,   Bl + gb);                                          \
    }                                                                          \
    asm volatile("cp.async.commit_group;"); }

    LOADSTAGE(0, 0);
    if (nK > 1) LOADSTAGE(1, 1);

    for (int kb = 0; kb < nK; ++kb) {
        int st = kb & 1;
        if (kb + 1 < nK) asm volatile("cp.async.wait_group 1;");
        else             asm volatile("cp.async.wait_group 0;");
        __syncthreads();

        uint32_t so = sb + st * STAGEB;
        #pragma unroll
        for (int ks = 0; ks < 2; ++ks) {
            uint32_t ah[4][4], al[4][4], bh[4][2], bl[4][2];
            #pragma unroll
            for (int mi = 0; mi < 4; ++mi) {
                uint32_t off = ((wm*64 + mi*16 + l15) * ROWH + ks*16 + aKsel) * 2;
                ldm4(ah[mi], so + off);
                if (TERMS == 3) ldm4(al[mi], so + MATB + off);
            }
            #pragma unroll
            for (int np = 0; np < 2; ++np) {
                uint32_t off = ((wn*32 + np*16 + ((lane >> 4) << 3) + (lane & 7)) * ROWH
                                + ks*16 + ((lane >> 3) & 1) * 8) * 2;
                uint32_t t0[4], t1[4];
                ldm4(t0, so + 2*MATB + off);
                ldm4(t1, so + 3*MATB + off);
                bh[2*np][0] = t0[0]; bh[2*np][1] = t0[1];
                bh[2*np+1][0] = t0[2]; bh[2*np+1][1] = t0[3];
                bl[2*np][0] = t1[0]; bl[2*np][1] = t1[1];
                bl[2*np+1][0] = t1[2]; bl[2*np+1][1] = t1[3];
            }
            #pragma unroll
            for (int mi = 0; mi < 4; ++mi)
                #pragma unroll
                for (int ni = 0; ni < 4; ++ni) {
                    mma16816(acc[mi][ni], ah[mi], bh[ni]);
                    mma16816(acc[mi][ni], ah[mi], bl[ni]);
                    if (TERMS == 3) mma16816(acc[mi][ni], al[mi], bh[ni]);
                }
        }
        __syncthreads();
        if (kb + 2 < nK) LOADSTAGE(st, kb + 2);
    }
#undef LOADSTAGE

    // ---------------- epilogue ----------------
    float* cs = (float*)smc;             // per-CTA column sums (MODE 1)
    if (MODE == 1) {
        if (tid < 128) cs[tid] = 0.f;
        __syncthreads();
    }

    #pragma unroll
    for (int mi = 0; mi < 4; ++mi)
        #pragma unroll
        for (int ni = 0; ni < 4; ++ni) {
            int r0 = m0 + wm*64 + mi*16 + (lane >> 2);
            int cl = wn*32 + ni*8 + (lane & 3) * 2;
            int c  = n0 + cl;
            float s0 = 0.f, s1 = 0.f;
            #pragma unroll
            for (int hr = 0; hr < 2; ++hr) {
                int r = r0 + hr * 8;
                float v0 = acc[mi][ni][hr*2 + 0];
                float v1 = acc[mi][ni][hr*2 + 1];
                if (MODE == 0 || MODE == 3) { v0 += __ldg(bias + c); v1 += __ldg(bias + c + 1); }
                if (MODE == 1) {
                    v0 = (r <= c)     ? __expf(v0 * scale) : 0.f;
                    v1 = (r <= c + 1) ? __expf(v1 * scale) : 0.f;
                    s0 += v0; s1 += v1;
                }
                if (MODE == 0) {
                    __half h0 = __float2half(v0), h1 = __float2half(v1);
                    __half l0 = __float2half(v0 - __half2float(h0));
                    __half l1 = __float2half(v1 - __half2float(h1));
                    *(__half2*)(Oh + (long long)r * ldo + c) = __halves2half2(h0, h1);
                    *(__half2*)(Ol + (long long)r * ldo + c) = __halves2half2(l0, l1);
                } else if (MODE == 2) {
                    float* p = Of + (long long)r * ldo + c;
                    if (atomicOut) { atomicAdd(p, v0); atomicAdd(p + 1, v1); }
                    else           *(float2*)p = make_float2(v0, v1);
                } else {
                    *(float2*)(Of + (long long)r * ldo + c) = make_float2(v0, v1);
                }
            }
            if (MODE == 1) { atomicAdd(&cs[cl], s0); atomicAdd(&cs[cl + 1], s1); }
        }

    if (MODE == 1) {
        __syncthreads();
        if (tid < 128) atomicAdd(&lsum[n0 + tid], cs[tid]);
    }
}

// ---------------- wrappers ---------------------------------------------------
struct ProjPtrs {
    const __half* ah[3]; const __half* al[3];
    const __half* bh[3]; const __half* bl[3];
    const float*  bias[3];
    __half* oh[3]; __half* ol[3]; float* of[3];
};

__global__ void __launch_bounds__(256, 2) gemm_proj(ProjPtrs P)
{
    int z = blockIdx.z;
    extern __shared__ __align__(16) char smc[];
    if (z == 2)
        gemm_body<3, 3>(P.ah[2], P.al[2], P.bh[2], P.bl[2], HID, HID,
                        blockIdx.y*128, blockIdx.x*128, 0, HID/BK, P.bias[2],
                        P.of[2], nullptr, nullptr, HID, 1.f, nullptr, 0, smc);
    else
        gemm_body<0, 3>(P.ah[z], P.al[z], P.bh[z], P.bl[z], HID, HID,
                        blockIdx.y*128, blockIdx.x*128, 0, HID/BK, P.bias[z],
                        nullptr, P.oh[z], P.ol[z], HID, 1.f, nullptr, 0, smc);
}

__global__ void __launch_bounds__(256, 2) gemm_scores(
    const __half* __restrict__ Kh, const __half* __restrict__ Qh,
    const __half* __restrict__ Ql, float* __restrict__ attn,
    float* __restrict__ lsum, float scale)
{
    if (blockIdx.y > blockIdx.x) return;         // fully-masked tile
    int bz = blockIdx.z;
    extern __shared__ __align__(16) char smc[];
    long long z = (long long)bz * SEQ * HID;
    gemm_body<1, 2>(Kh + z, nullptr, Qh + z, Ql + z, HID, HID,
                    blockIdx.y*128, blockIdx.x*128, 0, HID/BK, nullptr,
                    attn + (long long)bz*SEQ*SEQ, nullptr, nullptr, SEQ, scale,
                    lsum + bz*SEQ, 0, smc);
}

__global__ void __launch_bounds__(256, 2) gemm_ctx(
    const __half* __restrict__ ATh, const __half* __restrict__ Vth,
    const __half* __restrict__ Vtl, float* __restrict__ ctx)
{
    int by2 = blockIdx.y, bz = blockIdx.z;
    int by, half;
    if (by2 < 16) { by = 15 - (by2 >> 1); half = by2 & 1; }   // heavy tiles, split-K
    else          { by = 23 - by2;        half = -1;      }   // light tiles, full K
    int totK = 4 * (by + 1);
    int nK = (half >= 0) ? (totK >> 1) : totK;
    int kStart = (half > 0) ? nK : 0;
    extern __shared__ __align__(16) char smc[];
    gemm_body<2, 2>(ATh + (long long)bz*SEQ*SEQ, nullptr,
                    Vth + (long long)bz*HID*SEQ, Vtl + (long long)bz*HID*SEQ,
                    SEQ, SEQ, by*128, blockIdx.x*128, kStart, nK, nullptr,
                    ctx + (long long)bz*SEQ*HID, nullptr, nullptr, HID, 1.f,
                    nullptr, half >= 0 ? 1 : 0, smc);
}

// ---------------- fp32 -> fp16 hi/lo split (3 sources) ----------------------
__global__ void split3(const float* __restrict__ s0, const float* __restrict__ s1,
                       const float* __restrict__ s2, __half* __restrict__ h,
                       __half* __restrict__ l, long long perZ)
{
    int z = blockIdx.y;
    const float* s = (z == 0) ? s0 : ((z == 1) ? s1 : s2);
    long long i = ((long long)blockIdx.x * 256 + threadIdx.x) * 8;
    float4 a = *(const float4*)(s + i), b = *(const float4*)(s + i + 4);
    float v[8] = {a.x, a.y, a.z, a.w, b.x, b.y, b.z, b.w};
    union { uint4 u; __half e[8]; } H, L;
    #pragma unroll
    for (int j = 0; j < 8; ++j) {
        __half hh = __float2half(v[j]);
        H.e[j] = hh;
        L.e[j] = __float2half(v[j] - __half2float(hh));
    }
    *(uint4*)(h + z * perZ + i) = H.u;
    *(uint4*)(l + z * perZ + i) = L.u;
}

// ---------------- transpose + (optional) normalize + hi/lo split ------------
__global__ void pack_tr(const float* __restrict__ src, __half* __restrict__ dh,
                        __half* __restrict__ dl, int ldS, long long sZ, long long dZ,
                        const float* __restrict__ inv, float* __restrict__ wb, int causal)
{
    int kc = blockIdx.x, rt = blockIdx.y, bz = blockIdx.z;
    if (causal && kc * 64 > rt * 128 + 127) return;
    __shared__ float smt[64][129];
    const float* s = src + (long long)bz * sZ;
    int s0 = kc * 64, t0 = rt * 128;
    int tid = threadIdx.x;
    for (int i = 0; i < 32; ++i) {
        int idx = i * 256 + tid;
        int sr = idx >> 7, sc = idx & 127;
        float x = s[(long long)(s0 + sr) * ldS + t0 + sc];
        if (inv) {
            x *= inv[bz * SEQ + t0 + sc];
            wb[(long long)bz * sZ + (long long)(s0 + sr) * ldS + t0 + sc] = x;
        }
        smt[sr][sc] = x;
    }
    __syncthreads();
    int r = tid >> 1, half = tid & 1;
    long long db = (long long)bz * dZ + (long long)(t0 + r) * SEQ + s0 + half * 32;
    for (int g = 0; g < 4; ++g) {
        union { uint4 u; __half e[8]; } H, L;
        #pragma unroll
        for (int j = 0; j < 8; ++j) {
            float x = smt[half * 32 + g * 8 + j][r];
            __half hh = __float2half(x);
            H.e[j] = hh;
            if (dl) L.e[j] = __float2half(x - __half2float(hh));
        }
        *(uint4*)(dh + db + g * 8) = H.u;
        if (dl) *(uint4*)(dl + db + g * 8) = L.u;
    }
}

__global__ void invert(float* __restrict__ l)
{
    int i = blockIdx.x * 256 + threadIdx.x;
    l[i] = 1.0f / l[i];
}

// ---------------- launch -----------------------------------------------------
extern "C" void kernel_launch(void* const* d_in, const int* in_sizes, int n_in,
                              void* d_out, int out_size)
{
    const float* X[3]  = {(const float*)d_in[0], (const float*)d_in[1], (const float*)d_in[2]};
    const float* W[3]  = {(const float*)d_in[3], (const float*)d_in[5], (const float*)d_in[7]};
    const float* Bv[3] = {(const float*)d_in[4], (const float*)d_in[6], (const float*)d_in[8]};
    float* out = (float*)d_out;

    cudaFuncSetAttribute(gemm_proj,   cudaFuncAttributeMaxDynamicSharedMemorySize, SMTOT);
    cudaFuncSetAttribute(gemm_scores, cudaFuncAttributeMaxDynamicSharedMemorySize, SMTOT);
    cudaFuncSetAttribute(gemm_ctx,    cudaFuncAttributeMaxDynamicSharedMemorySize, SMTOT);

    __half *xh, *xl, *wh, *wl, *qh, *ql, *kh, *kl, *vth, *vtl, *ath;
    float *vf, *lsum, *attnScr;
    cudaGetSymbolAddress((void**)&xh, g_xh);   cudaGetSymbolAddress((void**)&xl, g_xl);
    cudaGetSymbolAddress((void**)&wh, g_wh);   cudaGetSymbolAddress((void**)&wl, g_wl);
    cudaGetSymbolAddress((void**)&qh, g_qh);   cudaGetSymbolAddress((void**)&ql, g_ql);
    cudaGetSymbolAddress((void**)&kh, g_kh);   cudaGetSymbolAddress((void**)&kl, g_kl);
    cudaGetSymbolAddress((void**)&vf, g_vf);
    cudaGetSymbolAddress((void**)&vth, g_vth); cudaGetSymbolAddress((void**)&vtl, g_vtl);
    cudaGetSymbolAddress((void**)&ath, g_ath);
    cudaGetSymbolAddress((void**)&lsum, g_l);  cudaGetSymbolAddress((void**)&attnScr, g_attn);

    const long long ctxElems  = (long long)BATCH * SEQ * HID;
    const long long attnElems = (long long)BATCH * SEQ * SEQ;
    float* ctx  = out;
    float* attn = ((long long)out_size >= ctxElems + attnElems) ? out + ctxElems : attnScr;

    const long long XPZ = (long long)RALL * HID, WPZ = (long long)HID * HID;
    const float scale = 0.03125f;   // 1/sqrt(1024)

    // 1) split inputs + weights to fp16 hi/lo
    split3<<<dim3((unsigned)(XPZ / 2048), 3), 256>>>(X[0], X[1], X[2], xh, xl, XPZ);
    split3<<<dim3((unsigned)(WPZ / 2048), 3), 256>>>(W[0], W[1], W[2], wh, wl, WPZ);

    // 2) projections (z = 0:Q, 1:K, 2:V), 3-term
    ProjPtrs P;
    for (int i = 0; i < 3; ++i) {
        P.ah[i] = xh + i * XPZ; P.al[i] = xl + i * XPZ;
        P.bh[i] = wh + i * WPZ; P.bl[i] = wl + i * WPZ;
        P.bias[i] = Bv[i];
        P.oh[i] = nullptr; P.ol[i] = nullptr; P.of[i] = nullptr;
    }
    P.oh[0] = qh; P.ol[0] = ql;
    P.oh[1] = kh; P.ol[1] = kl;
    P.of[2] = vf;
    gemm_proj<<<dim3(8, 64, 3), 256, SMTOT>>>(P);

    // 3) V^T pack per batch: VT[b][h][s] (hi + lo, both used by context)
    pack_tr<<<dim3(32, 8, BATCH), 256>>>(vf, vth, vtl, HID,
        (long long)SEQ * HID, (long long)HID * SEQ, nullptr, nullptr, 0);

    // 4) scores: attn[b,s,t] = exp(scale * <K_s, Q_t>), causal; fused colsum
    cudaMemsetAsync(attn, 0, attnElems * sizeof(float), 0);
    cudaMemsetAsync(lsum, 0, BATCH * SEQ * sizeof(float), 0);
    gemm_scores<<<dim3(16, 16, BATCH), 256, SMTOT>>>(kh, qh, ql, attn, lsum, scale);
    invert<<<BATCH * SEQ / 256, 256>>>(lsum);

    // 5) normalize attn in place + pack attn^T hi only (lo term dropped)
    pack_tr<<<dim3(32, 16, BATCH), 256>>>(attn, ath, nullptr, SEQ,
        (long long)SEQ * SEQ, (long long)SEQ * SEQ, lsum, attn, 1);

    // 6) context: ctx[b,t,h] = sum_s AT[t,s]*VT[h,s]; heavy tiles split-K
    cudaMemsetAsync(ctx, 0, ctxElems * sizeof(float), 0);
    gemm_ctx<<<dim3(8, 24, BATCH), 256, SMTOT>>>(ath, vth, vtl, ctx);
}

// round 11
// speedup vs baseline: 4.1269x; 1.2329x over previous
#include <cuda_runtime.h>
#include <cuda_fp16.h>
#include <cstdint>

#define SEQ   2048
#define HID   1024
#define BATCH 4
#define RALL  (BATCH*SEQ)          // 8192

// ---------------- device scratch --------------------------------------------
__device__ __align__(16) __half g_xh[3][(long long)RALL*HID];
__device__ __align__(16) __half g_wh[3][HID*HID];
__device__ __align__(16) __half g_wl[3][HID*HID];
__device__ __align__(16) __half g_qh[(long long)RALL*HID], g_ql[(long long)RALL*HID];
__device__ __align__(16) __half g_kh[(long long)RALL*HID];
__device__ float g_vf[(long long)RALL*HID];
__device__ __align__(16) __half g_vth[(long long)RALL*HID], g_vtl[(long long)RALL*HID];
__device__ __align__(16) __half g_ath[(long long)BATCH*SEQ*SEQ];
__device__ float g_attn[(long long)BATCH*SEQ*SEQ];
__device__ float g_l[BATCH*SEQ];

// ---------------- low-level helpers -----------------------------------------
__device__ __forceinline__ uint32_t smem_u32(const void* p){
    uint32_t a;
    asm("{ .reg .u64 t; cvta.to.shared.u64 t, %1; cvt.u32.u64 %0, t; }" : "=r"(a) : "l"(p));
    return a;
}
__device__ __forceinline__ void cp16(uint32_t d, const void* g){
    asm volatile("cp.async.cg.shared.global [%0], [%1], 16;" :: "r"(d), "l"(g));
}
__device__ __forceinline__ void ldm4(uint32_t* r, uint32_t a){
    asm volatile("ldmatrix.sync.aligned.m8n8.x4.shared.b16 {%0,%1,%2,%3}, [%4];"
        : "=r"(r[0]), "=r"(r[1]), "=r"(r[2]), "=r"(r[3]) : "r"(a));
}
__device__ __forceinline__ void mma16816(float* d, const uint32_t* a, const uint32_t* b){
    asm volatile("mma.sync.aligned.m16n8k16.row.col.f32.f16.f16.f32 "
        "{%0,%1,%2,%3}, {%4,%5,%6,%7}, {%8,%9}, {%0,%1,%2,%3};"
        : "+f"(d[0]), "+f"(d[1]), "+f"(d[2]), "+f"(d[3])
        : "r"(a[0]), "r"(a[1]), "r"(a[2]), "r"(a[3]), "r"(b[0]), "r"(b[1]));
}

#define BK     32
#define ROWH   40                  // fp16 elems per smem row (32 + 8 pad, 80B stride)
#define MATB   (128*ROWH*2)        // 10240 B per matrix tile
#define STAGEB (4*MATB)            // Ah, (Al), Bh, Bl slots = 40960 B
#define NSTAGE 2
#define SMTOT  (NSTAGE*STAGEB)     // 81920 B -> 2 CTAs/SM

// ---------------- shared GEMM body ------------------------------------------
// C[128x128]; NT: C[m,n] = sum_k A[m,k]*B[n,k]; fp16 hi/lo split, 2 terms:
// ah*bh + ah*bl  (A-lo never loaded).
// MODE: 0 = fp16 hi (+optional lo) out + bias, 1 = exp(scale*v) causal -> fp32
//       + fused colsum, 2 = fp32 out (optionally atomicAdd), 3 = fp32 + bias.
template<int MODE>
__device__ __forceinline__ void gemm_body(
    const __half* __restrict__ Ah,
    const __half* __restrict__ Bh, const __half* __restrict__ Bl,
    int ldA, int ldB, int m0, int n0, int kStart, int nK,
    const float* __restrict__ bias,
    float* __restrict__ Of, __half* __restrict__ Oh, __half* __restrict__ Ol,
    int ldo, float scale, float* __restrict__ lsum, int atomicOut, char* smc)
{
    uint32_t sb = smem_u32(smc);
    int tid = threadIdx.x, lane = tid & 31, w = tid >> 5;
    int wm = w & 1, wn = w >> 1;                 // 2 x 4 warp grid (m x n)

    float acc[4][4][4];
    #pragma unroll
    for (int i = 0; i < 4; ++i)
        #pragma unroll
        for (int j = 0; j < 4; ++j)
            #pragma unroll
            for (int u = 0; u < 4; ++u) acc[i][j][u] = 0.f;

    int l15 = lane & 15;
    int aKsel = (lane >> 4) * 8;

#define LOADSTAGE(st, kb) {                                                    \
    int k0 = (kStart + (kb)) * BK;                                             \
    uint32_t so_ = sb + (st) * STAGEB;                                         \
    _Pragma("unroll") for (int i = 0; i < 2; ++i) {                            \
        int c = tid + i * 256; int row = c >> 2, seg = c & 3;                  \
        uint32_t sd = so_ + row * 80 + seg * 16;                               \
        long long ga = (long long)(m0 + row) * ldA + k0 + seg * 8;             \
        long long gb = (long long)(n0 + row) * ldB + k0 + seg * 8;             \
        cp16(sd,            Ah + ga);                                          \
        cp16(sd + 2*MATB,   Bh + gb);                                          \
        cp16(sd + 3*MATB,   Bl + gb);                                          \
    }                                                                          \
    asm volatile("cp.async.commit_group;"); }

    LOADSTAGE(0, 0);
    if (nK > 1) LOADSTAGE(1, 1);

    for (int kb = 0; kb < nK; ++kb) {
        int st = kb & 1;
        if (kb + 1 < nK) asm volatile("cp.async.wait_group 1;");
        else             asm volatile("cp.async.wait_group 0;");
        __syncthreads();

        uint32_t so = sb + st * STAGEB;
        #pragma unroll
        for (int ks = 0; ks < 2; ++ks) {
            uint32_t ah[4][4], bh[4][2], bl[4][2];
            #pragma unroll
            for (int mi = 0; mi < 4; ++mi) {
                uint32_t off = ((wm*64 + mi*16 + l15) * ROWH + ks*16 + aKsel) * 2;
                ldm4(ah[mi], so + off);
            }
            #pragma unroll
            for (int np = 0; np < 2; ++np) {
                uint32_t off = ((wn*32 + np*16 + ((lane >> 4) << 3) + (lane & 7)) * ROWH
                                + ks*16 + ((lane >> 3) & 1) * 8) * 2;
                uint32_t t0[4], t1[4];
                ldm4(t0, so + 2*MATB + off);
                ldm4(t1, so + 3*MATB + off);
                bh[2*np][0] = t0[0]; bh[2*np][1] = t0[1];
                bh[2*np+1][0] = t0[2]; bh[2*np+1][1] = t0[3];
                bl[2*np][0] = t1[0]; bl[2*np][1] = t1[1];
                bl[2*np+1][0] = t1[2]; bl[2*np+1][1] = t1[3];
            }
            #pragma unroll
            for (int mi = 0; mi < 4; ++mi)
                #pragma unroll
                for (int ni = 0; ni < 4; ++ni) {
                    mma16816(acc[mi][ni], ah[mi], bh[ni]);
                    mma16816(acc[mi][ni], ah[mi], bl[ni]);
                }
        }
        __syncthreads();
        if (kb + 2 < nK) LOADSTAGE(st, kb + 2);
    }
#undef LOADSTAGE

    // ---------------- epilogue ----------------
    float* cs = (float*)smc;             // per-CTA column sums (MODE 1)
    if (MODE == 1) {
        if (tid < 128) cs[tid] = 0.f;
        __syncthreads();
    }

    #pragma unroll
    for (int mi = 0; mi < 4; ++mi)
        #pragma unroll
        for (int ni = 0; ni < 4; ++ni) {
            int r0 = m0 + wm*64 + mi*16 + (lane >> 2);
            int cl = wn*32 + ni*8 + (lane & 3) * 2;
            int c  = n0 + cl;
            float s0 = 0.f, s1 = 0.f;
            #pragma unroll
            for (int hr = 0; hr < 2; ++hr) {
                int r = r0 + hr * 8;
                float v0 = acc[mi][ni][hr*2 + 0];
                float v1 = acc[mi][ni][hr*2 + 1];
                if (MODE == 0 || MODE == 3) { v0 += __ldg(bias + c); v1 += __ldg(bias + c + 1); }
                if (MODE == 1) {
                    v0 = (r <= c)     ? __expf(v0 * scale) : 0.f;
                    v1 = (r <= c + 1) ? __expf(v1 * scale) : 0.f;
                    s0 += v0; s1 += v1;
                }
                if (MODE == 0) {
                    __half h0 = __float2half(v0), h1 = __float2half(v1);
                    *(__half2*)(Oh + (long long)r * ldo + c) = __halves2half2(h0, h1);
                    if (Ol) {
                        __half l0 = __float2half(v0 - __half2float(h0));
                        __half l1 = __float2half(v1 - __half2float(h1));
                        *(__half2*)(Ol + (long long)r * ldo + c) = __halves2half2(l0, l1);
                    }
                } else if (MODE == 2) {
                    float* p = Of + (long long)r * ldo + c;
                    if (atomicOut) { atomicAdd(p, v0); atomicAdd(p + 1, v1); }
                    else           *(float2*)p = make_float2(v0, v1);
                } else {
                    *(float2*)(Of + (long long)r * ldo + c) = make_float2(v0, v1);
                }
            }
            if (MODE == 1) { atomicAdd(&cs[cl], s0); atomicAdd(&cs[cl + 1], s1); }
        }

    if (MODE == 1) {
        __syncthreads();
        if (tid < 128) atomicAdd(&lsum[n0 + tid], cs[tid]);
    }
}

// ---------------- wrappers ---------------------------------------------------
struct ProjPtrs {
    const __half* ah[3];
    const __half* bh[3]; const __half* bl[3];
    const float*  bias[3];
    __half* oh[3]; __half* ol[3]; float* of[3];
};

__global__ void __launch_bounds__(256, 2) gemm_proj(ProjPtrs P)
{
    int z = blockIdx.z;
    extern __shared__ __align__(16) char smc[];
    if (z == 2)
        gemm_body<3>(P.ah[2], P.bh[2], P.bl[2], HID, HID,
                     blockIdx.y*128, blockIdx.x*128, 0, HID/BK, P.bias[2],
                     P.of[2], nullptr, nullptr, HID, 1.f, nullptr, 0, smc);
    else
        gemm_body<0>(P.ah[z], P.bh[z], P.bl[z], HID, HID,
                     blockIdx.y*128, blockIdx.x*128, 0, HID/BK, P.bias[z],
                     nullptr, P.oh[z], P.ol[z], HID, 1.f, nullptr, 0, smc);
}

__global__ void __launch_bounds__(256, 2) gemm_scores(
    const __half* __restrict__ Kh, const __half* __restrict__ Qh,
    const __half* __restrict__ Ql, float* __restrict__ attn,
    float* __restrict__ lsum, float scale)
{
    if (blockIdx.y > blockIdx.x) return;         // fully-masked tile
    int bz = blockIdx.z;
    extern __shared__ __align__(16) char smc[];
    long long z = (long long)bz * SEQ * HID;
    gemm_body<1>(Kh + z, Qh + z, Ql + z, HID, HID,
                 blockIdx.y*128, blockIdx.x*128, 0, HID/BK, nullptr,
                 attn + (long long)bz*SEQ*SEQ, nullptr, nullptr, SEQ, scale,
                 lsum + bz*SEQ, 0, smc);
}

__global__ void __launch_bounds__(256, 2) gemm_ctx(
    const __half* __restrict__ ATh, const __half* __restrict__ Vth,
    const __half* __restrict__ Vtl, float* __restrict__ ctx)
{
    int by2 = blockIdx.y, bz = blockIdx.z;
    int by, half;
    if (by2 < 16) { by = 15 - (by2 >> 1); half = by2 & 1; }   // heavy tiles, split-K
    else          { by = 23 - by2;        half = -1;      }   // light tiles, full K
    int totK = 4 * (by + 1);
    int nK = (half >= 0) ? (totK >> 1) : totK;
    int kStart = (half > 0) ? nK : 0;
    extern __shared__ __align__(16) char smc[];
    gemm_body<2>(ATh + (long long)bz*SEQ*SEQ,
                 Vth + (long long)bz*HID*SEQ, Vtl + (long long)bz*HID*SEQ,
                 SEQ, SEQ, by*128, blockIdx.x*128, kStart, nK, nullptr,
                 ctx + (long long)bz*SEQ*HID, nullptr, nullptr, HID, 1.f,
                 nullptr, half >= 0 ? 1 : 0, smc);
}

// ---------------- fp32 -> fp16 hi (+optional lo) split (3 sources) ----------
__global__ void split3(const float* __restrict__ s0, const float* __restrict__ s1,
                       const float* __restrict__ s2, __half* __restrict__ h,
                       __half* __restrict__ l, long long perZ)
{
    int z = blockIdx.y;
    const float* s = (z == 0) ? s0 : ((z == 1) ? s1 : s2);
    long long i = ((long long)blockIdx.x * 256 + threadIdx.x) * 8;
    float4 a = *(const float4*)(s + i), b = *(const float4*)(s + i + 4);
    float v[8] = {a.x, a.y, a.z, a.w, b.x, b.y, b.z, b.w};
    union { uint4 u; __half e[8]; } H, L;
    #pragma unroll
    for (int j = 0; j < 8; ++j) {
        __half hh = __float2half(v[j]);
        H.e[j] = hh;
        if (l) L.e[j] = __float2half(v[j] - __half2float(hh));
    }
    *(uint4*)(h + z * perZ + i) = H.u;
    if (l) *(uint4*)(l + z * perZ + i) = L.u;
}

// ---------------- transpose + (optional) normalize + hi/lo split ------------
__global__ void pack_tr(const float* __restrict__ src, __half* __restrict__ dh,
                        __half* __restrict__ dl, int ldS, long long sZ, long long dZ,
                        const float* __restrict__ inv, float* __restrict__ wb, int causal)
{
    int kc = blockIdx.x, rt = blockIdx.y, bz = blockIdx.z;
    if (causal && kc * 64 > rt * 128 + 127) return;
    __shared__ float smt[64][129];
    const float* s = src + (long long)bz * sZ;
    int s0 = kc * 64, t0 = rt * 128;
    int tid = threadIdx.x;
    for (int i = 0; i < 32; ++i) {
        int idx = i * 256 + tid;
        int sr = idx >> 7, sc = idx & 127;
        float x = s[(long long)(s0 + sr) * ldS + t0 + sc];
        if (inv) {
            x *= inv[bz * SEQ + t0 + sc];
            wb[(long long)bz * sZ + (long long)(s0 + sr) * ldS + t0 + sc] = x;
        }
        smt[sr][sc] = x;
    }
    __syncthreads();
    int r = tid >> 1, half = tid & 1;
    long long db = (long long)bz * dZ + (long long)(t0 + r) * SEQ + s0 + half * 32;
    for (int g = 0; g < 4; ++g) {
        union { uint4 u; __half e[8]; } H, L;
        #pragma unroll
        for (int j = 0; j < 8; ++j) {
            float x = smt[half * 32 + g * 8 + j][r];
            __half hh = __float2half(x);
            H.e[j] = hh;
            if (dl) L.e[j] = __float2half(x - __half2float(hh));
        }
        *(uint4*)(dh + db + g * 8) = H.u;
        if (dl) *(uint4*)(dl + db + g * 8) = L.u;
    }
}

__global__ void invert(float* __restrict__ l)
{
    int i = blockIdx.x * 256 + threadIdx.x;
    l[i] = 1.0f / l[i];
}

// ---------------- launch -----------------------------------------------------
extern "C" void kernel_launch(void* const* d_in, const int* in_sizes, int n_in,
                              void* d_out, int out_size)
{
    const float* X[3]  = {(const float*)d_in[0], (const float*)d_in[1], (const float*)d_in[2]};
    const float* W[3]  = {(const float*)d_in[3], (const float*)d_in[5], (const float*)d_in[7]};
    const float* Bv[3] = {(const float*)d_in[4], (const float*)d_in[6], (const float*)d_in[8]};
    float* out = (float*)d_out;

    cudaFuncSetAttribute(gemm_proj,   cudaFuncAttributeMaxDynamicSharedMemorySize, SMTOT);
    cudaFuncSetAttribute(gemm_scores, cudaFuncAttributeMaxDynamicSharedMemorySize, SMTOT);
    cudaFuncSetAttribute(gemm_ctx,    cudaFuncAttributeMaxDynamicSharedMemorySize, SMTOT);

    __half *xh, *wh, *wl, *qh, *ql, *kh, *vth, *vtl, *ath;
    float *vf, *lsum, *attnScr;
    cudaGetSymbolAddress((void**)&xh, g_xh);
    cudaGetSymbolAddress((void**)&wh, g_wh);   cudaGetSymbolAddress((void**)&wl, g_wl);
    cudaGetSymbolAddress((void**)&qh, g_qh);   cudaGetSymbolAddress((void**)&ql, g_ql);
    cudaGetSymbolAddress((void**)&kh, g_kh);
    cudaGetSymbolAddress((void**)&vf, g_vf);
    cudaGetSymbolAddress((void**)&vth, g_vth); cudaGetSymbolAddress((void**)&vtl, g_vtl);
    cudaGetSymbolAddress((void**)&ath, g_ath);
    cudaGetSymbolAddress((void**)&lsum, g_l);  cudaGetSymbolAddress((void**)&attnScr, g_attn);

    const long long ctxElems  = (long long)BATCH * SEQ * HID;
    const long long attnElems = (long long)BATCH * SEQ * SEQ;
    float* ctx  = out;
    float* attn = ((long long)out_size >= ctxElems + attnElems) ? out + ctxElems : attnScr;

    const long long XPZ = (long long)RALL * HID, WPZ = (long long)HID * HID;
    const float scale = 0.03125f;   // 1/sqrt(1024)

    // 1) split inputs (hi only; X-lo is dead) + weights (hi/lo)
    split3<<<dim3((unsigned)(XPZ / 2048), 3), 256>>>(X[0], X[1], X[2], xh, nullptr, XPZ);
    split3<<<dim3((unsigned)(WPZ / 2048), 3), 256>>>(W[0], W[1], W[2], wh, wl, WPZ);

    // 2) projections (z = 0:Q hi+lo, 1:K hi only, 2:V fp32), 2-term
    ProjPtrs P;
    for (int i = 0; i < 3; ++i) {
        P.ah[i] = xh + i * XPZ;
        P.bh[i] = wh + i * WPZ; P.bl[i] = wl + i * WPZ;
        P.bias[i] = Bv[i];
        P.oh[i] = nullptr; P.ol[i] = nullptr; P.of[i] = nullptr;
    }
    P.oh[0] = qh; P.ol[0] = ql;
    P.oh[1] = kh;                       // K-lo dead (K is always the hi operand)
    P.of[2] = vf;
    gemm_proj<<<dim3(8, 64, 3), 256, SMTOT>>>(P);

    // 3) V^T pack per batch: VT[b][h][s] (hi + lo)
    pack_tr<<<dim3(32, 8, BATCH), 256>>>(vf, vth, vtl, HID,
        (long long)SEQ * HID, (long long)HID * SEQ, nullptr, nullptr, 0);

    // 4) scores: attn[b,s,t] = exp(scale * <K_s, Q_t>), causal; fused colsum
    cudaMemsetAsync(attn, 0, attnElems * sizeof(float), 0);
    cudaMemsetAsync(lsum, 0, BATCH * SEQ * sizeof(float), 0);
    gemm_scores<<<dim3(16, 16, BATCH), 256, SMTOT>>>(kh, qh, ql, attn, lsum, scale);
    invert<<<BATCH * SEQ / 256, 256>>>(lsum);

    // 5) normalize attn in place + pack attn^T hi only
    pack_tr<<<dim3(32, 16, BATCH), 256>>>(attn, ath, nullptr, SEQ,
        (long long)SEQ * SEQ, (long long)SEQ * SEQ, lsum, attn, 1);

    // 6) context: ctx[b,t,h] = sum_s AT[t,s]*VT[h,s]; heavy tiles split-K
    cudaMemsetAsync(ctx, 0, ctxElems * sizeof(float), 0);
    gemm_ctx<<<dim3(8, 24, BATCH), 256, SMTOT>>>(ath, vth, vtl, ctx);
}

// round 12
// speedup vs baseline: 4.8408x; 1.1730x over previous
#include <cuda_runtime.h>
#include <cuda_fp16.h>
#include <cstdint>

#define SEQ   2048
#define HID   1024
#define BATCH 4
#define RALL  (BATCH*SEQ)          // 8192

// ---------------- device scratch --------------------------------------------
__device__ __align__(16) __half g_xh[3][(long long)RALL*HID];
__device__ __align__(16) __half g_wh[3][HID*HID];
__device__ __align__(16) __half g_wl[3][HID*HID];
__device__ __align__(16) __half g_qh[(long long)RALL*HID];
__device__ __align__(16) __half g_kh[(long long)RALL*HID];
__device__ float g_vf[(long long)RALL*HID];
__device__ __align__(16) __half g_vth[(long long)RALL*HID];
__device__ __align__(16) __half g_ath[(long long)BATCH*SEQ*SEQ];
__device__ float g_attn[(long long)BATCH*SEQ*SEQ];
__device__ float g_l[BATCH*SEQ];

// ---------------- low-level helpers -----------------------------------------
__device__ __forceinline__ uint32_t smem_u32(const void* p){
    uint32_t a;
    asm("{ .reg .u64 t; cvta.to.shared.u64 t, %1; cvt.u32.u64 %0, t; }" : "=r"(a) : "l"(p));
    return a;
}
__device__ __forceinline__ void cp16(uint32_t d, const void* g){
    asm volatile("cp.async.cg.shared.global [%0], [%1], 16;" :: "r"(d), "l"(g));
}
__device__ __forceinline__ void ldm4(uint32_t* r, uint32_t a){
    asm volatile("ldmatrix.sync.aligned.m8n8.x4.shared.b16 {%0,%1,%2,%3}, [%4];"
        : "=r"(r[0]), "=r"(r[1]), "=r"(r[2]), "=r"(r[3]) : "r"(a));
}
__device__ __forceinline__ void mma16816(float* d, const uint32_t* a, const uint32_t* b){
    asm volatile("mma.sync.aligned.m16n8k16.row.col.f32.f16.f16.f32 "
        "{%0,%1,%2,%3}, {%4,%5,%6,%7}, {%8,%9}, {%0,%1,%2,%3};"
        : "+f"(d[0]), "+f"(d[1]), "+f"(d[2]), "+f"(d[3])
        : "r"(a[0]), "r"(a[1]), "r"(a[2]), "r"(a[3]), "r"(b[0]), "r"(b[1]));
}

#define BK     32
#define ROWH   40                  // fp16 elems per smem row (32 + 8 pad, 80B stride)
#define MATB   (128*ROWH*2)        // 10240 B per matrix tile
#define STAGEB (4*MATB)            // Ah, -, Bh, Bl slots = 40960 B
#define NSTAGE 2
#define SMTOT  (NSTAGE*STAGEB)     // 81920 B -> 2 CTAs/SM

// ---------------- shared GEMM body ------------------------------------------
// C[128x128]; NT: C[m,n] = sum_k A[m,k]*B[n,k]; fp16 operands.
// BT=2: B = Bh + Bl (two MMA terms);  BT=1: B = Bh only (one term).
// MODE: 0 = fp16 hi (+opt lo) out + bias, 1 = exp(scale*v) causal -> fp32
//       + fused colsum, 2 = fp32 out (optionally atomicAdd), 3 = fp32 + bias.
template<int MODE, int BT>
__device__ __forceinline__ void gemm_body(
    const __half* __restrict__ Ah,
    const __half* __restrict__ Bh, const __half* __restrict__ Bl,
    int ldA, int ldB, int m0, int n0, int kStart, int nK,
    const float* __restrict__ bias,
    float* __restrict__ Of, __half* __restrict__ Oh, __half* __restrict__ Ol,
    int ldo, float scale, float* __restrict__ lsum, int atomicOut, char* smc)
{
    uint32_t sb = smem_u32(smc);
    int tid = threadIdx.x, lane = tid & 31, w = tid >> 5;
    int wm = w & 1, wn = w >> 1;                 // 2 x 4 warp grid (m x n)

    float acc[4][4][4];
    #pragma unroll
    for (int i = 0; i < 4; ++i)
        #pragma unroll
        for (int j = 0; j < 4; ++j)
            #pragma unroll
            for (int u = 0; u < 4; ++u) acc[i][j][u] = 0.f;

    int l15 = lane & 15;
    int aKsel = (lane >> 4) * 8;

#define LOADSTAGE(st, kb) {                                                    \
    int k0 = (kStart + (kb)) * BK;                                             \
    uint32_t so_ = sb + (st) * STAGEB;                                         \
    _Pragma("unroll") for (int i = 0; i < 2; ++i) {                            \
        int c = tid + i * 256; int row = c >> 2, seg = c & 3;                  \
        uint32_t sd = so_ + row * 80 + seg * 16;                               \
        long long ga = (long long)(m0 + row) * ldA + k0 + seg * 8;             \
        long long gb = (long long)(n0 + row) * ldB + k0 + seg * 8;             \
        cp16(sd,            Ah + ga);                                          \
        cp16(sd + 2*MATB,   Bh + gb);                                          \
        if (BT == 2) cp16(sd + 3*MATB, Bl + gb);                               \
    }                                                                          \
    asm volatile("cp.async.commit_group;"); }

    LOADSTAGE(0, 0);
    if (nK > 1) LOADSTAGE(1, 1);

    for (int kb = 0; kb < nK; ++kb) {
        int st = kb & 1;
        if (kb + 1 < nK) asm volatile("cp.async.wait_group 1;");
        else             asm volatile("cp.async.wait_group 0;");
        __syncthreads();

        uint32_t so = sb + st * STAGEB;
        #pragma unroll
        for (int ks = 0; ks < 2; ++ks) {
            uint32_t ah[4][4], bh[4][2], bl[4][2];
            #pragma unroll
            for (int mi = 0; mi < 4; ++mi) {
                uint32_t off = ((wm*64 + mi*16 + l15) * ROWH + ks*16 + aKsel) * 2;
                ldm4(ah[mi], so + off);
            }
            #pragma unroll
            for (int np = 0; np < 2; ++np) {
                uint32_t off = ((wn*32 + np*16 + ((lane >> 4) << 3) + (lane & 7)) * ROWH
                                + ks*16 + ((lane >> 3) & 1) * 8) * 2;
                uint32_t t0[4];
                ldm4(t0, so + 2*MATB + off);
                bh[2*np][0] = t0[0]; bh[2*np][1] = t0[1];
                bh[2*np+1][0] = t0[2]; bh[2*np+1][1] = t0[3];
                if (BT == 2) {
                    uint32_t t1[4];
                    ldm4(t1, so + 3*MATB + off);
                    bl[2*np][0] = t1[0]; bl[2*np][1] = t1[1];
                    bl[2*np+1][0] = t1[2]; bl[2*np+1][1] = t1[3];
                }
            }
            #pragma unroll
            for (int mi = 0; mi < 4; ++mi)
                #pragma unroll
                for (int ni = 0; ni < 4; ++ni) {
                    mma16816(acc[mi][ni], ah[mi], bh[ni]);
                    if (BT == 2) mma16816(acc[mi][ni], ah[mi], bl[ni]);
                }
        }
        __syncthreads();
        if (kb + 2 < nK) LOADSTAGE(st, kb + 2);
    }
#undef LOADSTAGE

    // ---------------- epilogue ----------------
    float* cs = (float*)smc;             // per-CTA column sums (MODE 1)
    if (MODE == 1) {
        if (tid < 128) cs[tid] = 0.f;
        __syncthreads();
    }

    #pragma unroll
    for (int mi = 0; mi < 4; ++mi)
        #pragma unroll
        for (int ni = 0; ni < 4; ++ni) {
            int r0 = m0 + wm*64 + mi*16 + (lane >> 2);
            int cl = wn*32 + ni*8 + (lane & 3) * 2;
            int c  = n0 + cl;
            float s0 = 0.f, s1 = 0.f;
            #pragma unroll
            for (int hr = 0; hr < 2; ++hr) {
                int r = r0 + hr * 8;
                float v0 = acc[mi][ni][hr*2 + 0];
                float v1 = acc[mi][ni][hr*2 + 1];
                if (MODE == 0 || MODE == 3) { v0 += __ldg(bias + c); v1 += __ldg(bias + c + 1); }
                if (MODE == 1) {
                    v0 = (r <= c)     ? __expf(v0 * scale) : 0.f;
                    v1 = (r <= c + 1) ? __expf(v1 * scale) : 0.f;
                    s0 += v0; s1 += v1;
                }
                if (MODE == 0) {
                    __half h0 = __float2half(v0), h1 = __float2half(v1);
                    *(__half2*)(Oh + (long long)r * ldo + c) = __halves2half2(h0, h1);
                    if (Ol) {
                        __half l0 = __float2half(v0 - __half2float(h0));
                        __half l1 = __float2half(v1 - __half2float(h1));
                        *(__half2*)(Ol + (long long)r * ldo + c) = __halves2half2(l0, l1);
                    }
                } else if (MODE == 2) {
                    float* p = Of + (long long)r * ldo + c;
                    if (atomicOut) { atomicAdd(p, v0); atomicAdd(p + 1, v1); }
                    else           *(float2*)p = make_float2(v0, v1);
                } else {
                    *(float2*)(Of + (long long)r * ldo + c) = make_float2(v0, v1);
                }
            }
            if (MODE == 1) { atomicAdd(&cs[cl], s0); atomicAdd(&cs[cl + 1], s1); }
        }

    if (MODE == 1) {
        __syncthreads();
        if (tid < 128) atomicAdd(&lsum[n0 + tid], cs[tid]);
    }
}

// ---------------- wrappers ---------------------------------------------------
struct ProjPtrs {
    const __half* ah[3];
    const __half* bh[3]; const __half* bl[3];
    const float*  bias[3];
    __half* oh[3]; float* of[3];
};

__global__ void __launch_bounds__(256, 2) gemm_proj(ProjPtrs P)
{
    int z = blockIdx.z;
    extern __shared__ __align__(16) char smc[];
    if (z == 2)
        gemm_body<3, 2>(P.ah[2], P.bh[2], P.bl[2], HID, HID,
                        blockIdx.y*128, blockIdx.x*128, 0, HID/BK, P.bias[2],
                        P.of[2], nullptr, nullptr, HID, 1.f, nullptr, 0, smc);
    else
        gemm_body<0, 2>(P.ah[z], P.bh[z], P.bl[z], HID, HID,
                        blockIdx.y*128, blockIdx.x*128, 0, HID/BK, P.bias[z],
                        nullptr, P.oh[z], nullptr, HID, 1.f, nullptr, 0, smc);
}

__global__ void __launch_bounds__(256, 2) gemm_scores(
    const __half* __restrict__ Kh, const __half* __restrict__ Qh,
    float* __restrict__ attn, float* __restrict__ lsum, float scale)
{
    if (blockIdx.y > blockIdx.x) return;         // fully-masked tile
    int bz = blockIdx.z;
    extern __shared__ __align__(16) char smc[];
    long long z = (long long)bz * SEQ * HID;
    gemm_body<1, 1>(Kh + z, Qh + z, nullptr, HID, HID,
                    blockIdx.y*128, blockIdx.x*128, 0, HID/BK, nullptr,
                    attn + (long long)bz*SEQ*SEQ, nullptr, nullptr, SEQ, scale,
                    lsum + bz*SEQ, 0, smc);
}

__global__ void __launch_bounds__(256, 2) gemm_ctx(
    const __half* __restrict__ ATh, const __half* __restrict__ Vth,
    float* __restrict__ ctx)
{
    int by2 = blockIdx.y, bz = blockIdx.z;
    int by, half;
    if (by2 < 16) { by = 15 - (by2 >> 1); half = by2 & 1; }   // heavy tiles, split-K
    else          { by = 23 - by2;        half = -1;      }   // light tiles, full K
    int totK = 4 * (by + 1);
    int nK = (half >= 0) ? (totK >> 1) : totK;
    int kStart = (half > 0) ? nK : 0;
    extern __shared__ __align__(16) char smc[];
    gemm_body<2, 1>(ATh + (long long)bz*SEQ*SEQ,
                    Vth + (long long)bz*HID*SEQ, nullptr,
                    SEQ, SEQ, by*128, blockIdx.x*128, kStart, nK, nullptr,
                    ctx + (long long)bz*SEQ*HID, nullptr, nullptr, HID, 1.f,
                    nullptr, half >= 0 ? 1 : 0, smc);
}

// ---------------- fp32 -> fp16 hi (+optional lo) split (3 sources) ----------
__global__ void split3(const float* __restrict__ s0, const float* __restrict__ s1,
                       const float* __restrict__ s2, __half* __restrict__ h,
                       __half* __restrict__ l, long long perZ)
{
    int z = blockIdx.y;
    const float* s = (z == 0) ? s0 : ((z == 1) ? s1 : s2);
    long long i = ((long long)blockIdx.x * 256 + threadIdx.x) * 8;
    float4 a = *(const float4*)(s + i), b = *(const float4*)(s + i + 4);
    float v[8] = {a.x, a.y, a.z, a.w, b.x, b.y, b.z, b.w};
    union { uint4 u; __half e[8]; } H, L;
    #pragma unroll
    for (int j = 0; j < 8; ++j) {
        __half hh = __float2half(v[j]);
        H.e[j] = hh;
        if (l) L.e[j] = __float2half(v[j] - __half2float(hh));
    }
    *(uint4*)(h + z * perZ + i) = H.u;
    if (l) *(uint4*)(l + z * perZ + i) = L.u;
}

// ---------------- transpose + (optional) normalize + fp16 pack --------------
__global__ void pack_tr(const float* __restrict__ src, __half* __restrict__ dh,
                        int ldS, long long sZ, long long dZ,
                        const float* __restrict__ inv, float* __restrict__ wb, int causal)
{
    int kc = blockIdx.x, rt = blockIdx.y, bz = blockIdx.z;
    if (causal && kc * 64 > rt * 128 + 127) return;
    __shared__ float smt[64][129];
    const float* s = src + (long long)bz * sZ;
    int s0 = kc * 64, t0 = rt * 128;
    int tid = threadIdx.x;
    for (int i = 0; i < 32; ++i) {
        int idx = i * 256 + tid;
        int sr = idx >> 7, sc = idx & 127;
        float x = s[(long long)(s0 + sr) * ldS + t0 + sc];
        if (inv) {
            x *= inv[bz * SEQ + t0 + sc];
            wb[(long long)bz * sZ + (long long)(s0 + sr) * ldS + t0 + sc] = x;
        }
        smt[sr][sc] = x;
    }
    __syncthreads();
    int r = tid >> 1, half = tid & 1;
    long long db = (long long)bz * dZ + (long long)(t0 + r) * SEQ + s0 + half * 32;
    for (int g = 0; g < 4; ++g) {
        union { uint4 u; __half e[8]; } H;
        #pragma unroll
        for (int j = 0; j < 8; ++j)
            H.e[j] = __float2half(smt[half * 32 + g * 8 + j][r]);
        *(uint4*)(dh + db + g * 8) = H.u;
    }
}

__global__ void invert(float* __restrict__ l)
{
    int i = blockIdx.x * 256 + threadIdx.x;
    l[i] = 1.0f / l[i];
}

// ---------------- launch -----------------------------------------------------
extern "C" void kernel_launch(void* const* d_in, const int* in_sizes, int n_in,
                              void* d_out, int out_size)
{
    const float* X[3]  = {(const float*)d_in[0], (const float*)d_in[1], (const float*)d_in[2]};
    const float* W[3]  = {(const float*)d_in[3], (const float*)d_in[5], (const float*)d_in[7]};
    const float* Bv[3] = {(const float*)d_in[4], (const float*)d_in[6], (const float*)d_in[8]};
    float* out = (float*)d_out;

    cudaFuncSetAttribute(gemm_proj,   cudaFuncAttributeMaxDynamicSharedMemorySize, SMTOT);
    cudaFuncSetAttribute(gemm_scores, cudaFuncAttributeMaxDynamicSharedMemorySize, SMTOT);
    cudaFuncSetAttribute(gemm_ctx,    cudaFuncAttributeMaxDynamicSharedMemorySize, SMTOT);

    __half *xh, *wh, *wl, *qh, *kh, *vth, *ath;
    float *vf, *lsum, *attnScr;
    cudaGetSymbolAddress((void**)&xh, g_xh);
    cudaGetSymbolAddress((void**)&wh, g_wh);   cudaGetSymbolAddress((void**)&wl, g_wl);
    cudaGetSymbolAddress((void**)&qh, g_qh);   cudaGetSymbolAddress((void**)&kh, g_kh);
    cudaGetSymbolAddress((void**)&vf, g_vf);   cudaGetSymbolAddress((void**)&vth, g_vth);
    cudaGetSymbolAddress((void**)&ath, g_ath);
    cudaGetSymbolAddress((void**)&lsum, g_l);  cudaGetSymbolAddress((void**)&attnScr, g_attn);

    const long long ctxElems  = (long long)BATCH * SEQ * HID;
    const long long attnElems = (long long)BATCH * SEQ * SEQ;
    float* ctx  = out;
    float* attn = ((long long)out_size >= ctxElems + attnElems) ? out + ctxElems : attnScr;

    const long long XPZ = (long long)RALL * HID, WPZ = (long long)HID * HID;
    const float scale = 0.03125f;   // 1/sqrt(1024)

    // 1) split inputs (hi only) + weights (hi/lo)
    split3<<<dim3((unsigned)(XPZ / 2048), 3), 256>>>(X[0], X[1], X[2], xh, nullptr, XPZ);
    split3<<<dim3((unsigned)(WPZ / 2048), 3), 256>>>(W[0], W[1], W[2], wh, wl, WPZ);

    // 2) projections (z = 0:Q hi, 1:K hi, 2:V fp32), 2-term (W hi+lo)
    ProjPtrs P;
    for (int i = 0; i < 3; ++i) {
        P.ah[i] = xh + i * XPZ;
        P.bh[i] = wh + i * WPZ; P.bl[i] = wl + i * WPZ;
        P.bias[i] = Bv[i];
        P.oh[i] = nullptr; P.of[i] = nullptr;
    }
    P.oh[0] = qh;
    P.oh[1] = kh;
    P.of[2] = vf;
    gemm_proj<<<dim3(8, 64, 3), 256, SMTOT>>>(P);

    // 3) V^T pack per batch: VT[b][h][s] (hi only)
    pack_tr<<<dim3(32, 8, BATCH), 256>>>(vf, vth, HID,
        (long long)SEQ * HID, (long long)HID * SEQ, nullptr, nullptr, 0);

    // 4) scores: attn[b,s,t] = exp(scale * <K_s, Q_t>), causal; fused colsum
    cudaMemsetAsync(attn, 0, attnElems * sizeof(float), 0);
    cudaMemsetAsync(lsum, 0, BATCH * SEQ * sizeof(float), 0);
    gemm_scores<<<dim3(16, 16, BATCH), 256, SMTOT>>>(kh, qh, attn, lsum, scale);
    invert<<<BATCH * SEQ / 256, 256>>>(lsum);

    // 5) normalize attn in place + pack attn^T (hi only)
    pack_tr<<<dim3(32, 16, BATCH), 256>>>(attn, ath, SEQ,
        (long long)SEQ * SEQ, (long long)SEQ * SEQ, lsum, attn, 1);

    // 6) context: ctx[b,t,h] = sum_s AT[t,s]*VT[h,s]; heavy tiles split-K
    cudaMemsetAsync(ctx, 0, ctxElems * sizeof(float), 0);
    gemm_ctx<<<dim3(8, 24, BATCH), 256, SMTOT>>>(ath, vth, ctx);
}

// round 13
// speedup vs baseline: 5.9807x; 1.2355x over previous
#include <cuda_runtime.h>
#include <cuda_fp16.h>
#include <cstdint>

#define SEQ   2048
#define HID   1024
#define BATCH 4
#define RALL  (BATCH*SEQ)          // 8192

// ---------------- device scratch --------------------------------------------
__device__ __align__(16) __half g_xh[3][(long long)RALL*HID];
__device__ __align__(16) __half g_wh[3][HID*HID];
__device__ __align__(16) __half g_qh[(long long)RALL*HID];
__device__ __align__(16) __half g_kh[(long long)RALL*HID];
__device__ float g_vf[(long long)RALL*HID];
__device__ __align__(16) __half g_vth[(long long)RALL*HID];
__device__ __align__(16) __half g_ath[(long long)BATCH*SEQ*SEQ];
__device__ float g_attn[(long long)BATCH*SEQ*SEQ];
__device__ float g_l[BATCH*SEQ];

// ---------------- low-level helpers -----------------------------------------
__device__ __forceinline__ uint32_t smem_u32(const void* p){
    uint32_t a;
    asm("{ .reg .u64 t; cvta.to.shared.u64 t, %1; cvt.u32.u64 %0, t; }" : "=r"(a) : "l"(p));
    return a;
}
__device__ __forceinline__ void cp16(uint32_t d, const void* g){
    asm volatile("cp.async.cg.shared.global [%0], [%1], 16;" :: "r"(d), "l"(g));
}
__device__ __forceinline__ void ldm4(uint32_t* r, uint32_t a){
    asm volatile("ldmatrix.sync.aligned.m8n8.x4.shared.b16 {%0,%1,%2,%3}, [%4];"
        : "=r"(r[0]), "=r"(r[1]), "=r"(r[2]), "=r"(r[3]) : "r"(a));
}
__device__ __forceinline__ void mma16816(float* d, const uint32_t* a, const uint32_t* b){
    asm volatile("mma.sync.aligned.m16n8k16.row.col.f32.f16.f16.f32 "
        "{%0,%1,%2,%3}, {%4,%5,%6,%7}, {%8,%9}, {%0,%1,%2,%3};"
        : "+f"(d[0]), "+f"(d[1]), "+f"(d[2]), "+f"(d[3])
        : "r"(a[0]), "r"(a[1]), "r"(a[2]), "r"(a[3]), "r"(b[0]), "r"(b[1]));
}

#define BK     32
#define ROWH   40                  // fp16 elems per smem row (32 + 8 pad, 80B stride)
#define MATB   (128*ROWH*2)        // 10240 B per matrix tile
#define STAGEB (2*MATB)            // Ah, Bh = 20480 B
#define NSTAGE 2
#define SMTOT  (NSTAGE*STAGEB)     // 40960 B -> 2 CTAs/SM (regs are the limit)

// ---------------- shared GEMM body ------------------------------------------
// C[128x128]; NT: C[m,n] = sum_k A[m,k]*B[n,k]; pure fp16 operands, fp32 acc.
// MODE: 0 = fp16 out + bias, 1 = exp(scale*v) causal -> fp32 + fused colsum,
//       2 = fp32 out (optionally atomicAdd), 3 = fp32 + bias.
template<int MODE>
__device__ __forceinline__ void gemm_body(
    const __half* __restrict__ Ah, const __half* __restrict__ Bh,
    int ldA, int ldB, int m0, int n0, int kStart, int nK,
    const float* __restrict__ bias,
    float* __restrict__ Of, __half* __restrict__ Oh,
    int ldo, float scale, float* __restrict__ lsum, int atomicOut, char* smc)
{
    uint32_t sb = smem_u32(smc);
    int tid = threadIdx.x, lane = tid & 31, w = tid >> 5;
    int wm = w & 1, wn = w >> 1;                 // 2 x 4 warp grid (m x n)

    float acc[4][4][4];
    #pragma unroll
    for (int i = 0; i < 4; ++i)
        #pragma unroll
        for (int j = 0; j < 4; ++j)
            #pragma unroll
            for (int u = 0; u < 4; ++u) acc[i][j][u] = 0.f;

    int l15 = lane & 15;
    int aKsel = (lane >> 4) * 8;

#define LOADSTAGE(st, kb) {                                                    \
    int k0 = (kStart + (kb)) * BK;                                             \
    uint32_t so_ = sb + (st) * STAGEB;                                         \
    _Pragma("unroll") for (int i = 0; i < 2; ++i) {                            \
        int c = tid + i * 256; int row = c >> 2, seg = c & 3;                  \
        uint32_t sd = so_ + row * 80 + seg * 16;                               \
        long long ga = (long long)(m0 + row) * ldA + k0 + seg * 8;             \
        long long gb = (long long)(n0 + row) * ldB + k0 + seg * 8;             \
        cp16(sd,        Ah + ga);                                              \
        cp16(sd + MATB, Bh + gb);                                              \
    }                                                                          \
    asm volatile("cp.async.commit_group;"); }

    LOADSTAGE(0, 0);
    if (nK > 1) LOADSTAGE(1, 1);

    for (int kb = 0; kb < nK; ++kb) {
        int st = kb & 1;
        if (kb + 1 < nK) asm volatile("cp.async.wait_group 1;");
        else             asm volatile("cp.async.wait_group 0;");
        __syncthreads();

        uint32_t so = sb + st * STAGEB;
        #pragma unroll
        for (int ks = 0; ks < 2; ++ks) {
            uint32_t ah[4][4], bh[4][2];
            #pragma unroll
            for (int mi = 0; mi < 4; ++mi) {
                uint32_t off = ((wm*64 + mi*16 + l15) * ROWH + ks*16 + aKsel) * 2;
                ldm4(ah[mi], so + off);
            }
            #pragma unroll
            for (int np = 0; np < 2; ++np) {
                uint32_t off = ((wn*32 + np*16 + ((lane >> 4) << 3) + (lane & 7)) * ROWH
                                + ks*16 + ((lane >> 3) & 1) * 8) * 2;
                uint32_t t0[4];
                ldm4(t0, so + MATB + off);
                bh[2*np][0] = t0[0]; bh[2*np][1] = t0[1];
                bh[2*np+1][0] = t0[2]; bh[2*np+1][1] = t0[3];
            }
            #pragma unroll
            for (int mi = 0; mi < 4; ++mi)
                #pragma unroll
                for (int ni = 0; ni < 4; ++ni)
                    mma16816(acc[mi][ni], ah[mi], bh[ni]);
        }
        __syncthreads();
        if (kb + 2 < nK) LOADSTAGE(st, kb + 2);
    }
#undef LOADSTAGE

    // ---------------- epilogue ----------------
    float* cs = (float*)smc;             // per-CTA column sums (MODE 1)
    if (MODE == 1) {
        if (tid < 128) cs[tid] = 0.f;
        __syncthreads();
    }

    #pragma unroll
    for (int mi = 0; mi < 4; ++mi)
        #pragma unroll
        for (int ni = 0; ni < 4; ++ni) {
            int r0 = m0 + wm*64 + mi*16 + (lane >> 2);
            int cl = wn*32 + ni*8 + (lane & 3) * 2;
            int c  = n0 + cl;
            float s0 = 0.f, s1 = 0.f;
            #pragma unroll
            for (int hr = 0; hr < 2; ++hr) {
                int r = r0 + hr * 8;
                float v0 = acc[mi][ni][hr*2 + 0];
                float v1 = acc[mi][ni][hr*2 + 1];
                if (MODE == 0 || MODE == 3) { v0 += __ldg(bias + c); v1 += __ldg(bias + c + 1); }
                if (MODE == 1) {
                    v0 = (r <= c)     ? __expf(v0 * scale) : 0.f;
                    v1 = (r <= c + 1) ? __expf(v1 * scale) : 0.f;
                    s0 += v0; s1 += v1;
                }
                if (MODE == 0) {
                    *(__half2*)(Oh + (long long)r * ldo + c)
                        = __halves2half2(__float2half(v0), __float2half(v1));
                } else if (MODE == 2) {
                    float* p = Of + (long long)r * ldo + c;
                    if (atomicOut) { atomicAdd(p, v0); atomicAdd(p + 1, v1); }
                    else           *(float2*)p = make_float2(v0, v1);
                } else {
                    *(float2*)(Of + (long long)r * ldo + c) = make_float2(v0, v1);
                }
            }
            if (MODE == 1) { atomicAdd(&cs[cl], s0); atomicAdd(&cs[cl + 1], s1); }
        }

    if (MODE == 1) {
        __syncthreads();
        if (tid < 128) atomicAdd(&lsum[n0 + tid], cs[tid]);
    }
}

// ---------------- wrappers ---------------------------------------------------
struct ProjPtrs {
    const __half* ah[3];
    const __half* bh[3];
    const float*  bias[3];
    __half* oh[3]; float* of[3];
};

__global__ void __launch_bounds__(256, 2) gemm_proj(ProjPtrs P)
{
    int z = blockIdx.z;
    extern __shared__ __align__(16) char smc[];
    if (z == 2)
        gemm_body<3>(P.ah[2], P.bh[2], HID, HID,
                     blockIdx.y*128, blockIdx.x*128, 0, HID/BK, P.bias[2],
                     P.of[2], nullptr, HID, 1.f, nullptr, 0, smc);
    else
        gemm_body<0>(P.ah[z], P.bh[z], HID, HID,
                     blockIdx.y*128, blockIdx.x*128, 0, HID/BK, P.bias[z],
                     nullptr, P.oh[z], HID, 1.f, nullptr, 0, smc);
}

__global__ void __launch_bounds__(256, 2) gemm_scores(
    const __half* __restrict__ Kh, const __half* __restrict__ Qh,
    float* __restrict__ attn, float* __restrict__ lsum, float scale)
{
    if (blockIdx.y > blockIdx.x) return;         // fully-masked tile
    int bz = blockIdx.z;
    extern __shared__ __align__(16) char smc[];
    long long z = (long long)bz * SEQ * HID;
    gemm_body<1>(Kh + z, Qh + z, HID, HID,
                 blockIdx.y*128, blockIdx.x*128, 0, HID/BK, nullptr,
                 attn + (long long)bz*SEQ*SEQ, nullptr, SEQ, scale,
                 lsum + bz*SEQ, 0, smc);
}

__global__ void __launch_bounds__(256, 2) gemm_ctx(
    const __half* __restrict__ ATh, const __half* __restrict__ Vth,
    float* __restrict__ ctx)
{
    int by2 = blockIdx.y, bz = blockIdx.z;
    int by, half;
    if (by2 < 16) { by = 15 - (by2 >> 1); half = by2 & 1; }   // heavy tiles, split-K
    else          { by = 23 - by2;        half = -1;      }   // light tiles, full K
    int totK = 4 * (by + 1);
    int nK = (half >= 0) ? (totK >> 1) : totK;
    int kStart = (half > 0) ? nK : 0;
    extern __shared__ __align__(16) char smc[];
    gemm_body<2>(ATh + (long long)bz*SEQ*SEQ, Vth + (long long)bz*HID*SEQ,
                 SEQ, SEQ, by*128, blockIdx.x*128, kStart, nK, nullptr,
                 ctx + (long long)bz*SEQ*HID, nullptr, HID, 1.f,
                 nullptr, half >= 0 ? 1 : 0, smc);
}

// ---------------- fp32 -> fp16 convert (3 sources) ---------------------------
__global__ void split3(const float* __restrict__ s0, const float* __restrict__ s1,
                       const float* __restrict__ s2, __half* __restrict__ h,
                       long long perZ)
{
    int z = blockIdx.y;
    const float* s = (z == 0) ? s0 : ((z == 1) ? s1 : s2);
    long long i = ((long long)blockIdx.x * 256 + threadIdx.x) * 8;
    float4 a = *(const float4*)(s + i), b = *(const float4*)(s + i + 4);
    float v[8] = {a.x, a.y, a.z, a.w, b.x, b.y, b.z, b.w};
    union { uint4 u; __half e[8]; } H;
    #pragma unroll
    for (int j = 0; j < 8; ++j) H.e[j] = __float2half(v[j]);
    *(uint4*)(h + z * perZ + i) = H.u;
}

// ---------------- transpose + (optional) normalize + fp16 pack --------------
__global__ void pack_tr(const float* __restrict__ src, __half* __restrict__ dh,
                        int ldS, long long sZ, long long dZ,
                        const float* __restrict__ inv, float* __restrict__ wb, int causal)
{
    int kc = blockIdx.x, rt = blockIdx.y, bz = blockIdx.z;
    if (causal && kc * 64 > rt * 128 + 127) return;
    __shared__ float smt[64][129];
    const float* s = src + (long long)bz * sZ;
    int s0 = kc * 64, t0 = rt * 128;
    int tid = threadIdx.x;
    for (int i = 0; i < 32; ++i) {
        int idx = i * 256 + tid;
        int sr = idx >> 7, sc = idx & 127;
        float x = s[(long long)(s0 + sr) * ldS + t0 + sc];
        if (inv) {
            x *= inv[bz * SEQ + t0 + sc];
            wb[(long long)bz * sZ + (long long)(s0 + sr) * ldS + t0 + sc] = x;
        }
        smt[sr][sc] = x;
    }
    __syncthreads();
    int r = tid >> 1, half = tid & 1;
    long long db = (long long)bz * dZ + (long long)(t0 + r) * SEQ + s0 + half * 32;
    for (int g = 0; g < 4; ++g) {
        union { uint4 u; __half e[8]; } H;
        #pragma unroll
        for (int j = 0; j < 8; ++j)
            H.e[j] = __float2half(smt[half * 32 + g * 8 + j][r]);
        *(uint4*)(dh + db + g * 8) = H.u;
    }
}

__global__ void invert(float* __restrict__ l)
{
    int i = blockIdx.x * 256 + threadIdx.x;
    l[i] = 1.0f / l[i];
}

// ---------------- launch -----------------------------------------------------
extern "C" void kernel_launch(void* const* d_in, const int* in_sizes, int n_in,
                              void* d_out, int out_size)
{
    const float* X[3]  = {(const float*)d_in[0], (const float*)d_in[1], (const float*)d_in[2]};
    const float* W[3]  = {(const float*)d_in[3], (const float*)d_in[5], (const float*)d_in[7]};
    const float* Bv[3] = {(const float*)d_in[4], (const float*)d_in[6], (const float*)d_in[8]};
    float* out = (float*)d_out;

    cudaFuncSetAttribute(gemm_proj,   cudaFuncAttributeMaxDynamicSharedMemorySize, SMTOT);
    cudaFuncSetAttribute(gemm_scores, cudaFuncAttributeMaxDynamicSharedMemorySize, SMTOT);
    cudaFuncSetAttribute(gemm_ctx,    cudaFuncAttributeMaxDynamicSharedMemorySize, SMTOT);

    __half *xh, *wh, *qh, *kh, *vth, *ath;
    float *vf, *lsum, *attnScr;
    cudaGetSymbolAddress((void**)&xh, g_xh);   cudaGetSymbolAddress((void**)&wh, g_wh);
    cudaGetSymbolAddress((void**)&qh, g_qh);   cudaGetSymbolAddress((void**)&kh, g_kh);
    cudaGetSymbolAddress((void**)&vf, g_vf);   cudaGetSymbolAddress((void**)&vth, g_vth);
    cudaGetSymbolAddress((void**)&ath, g_ath);
    cudaGetSymbolAddress((void**)&lsum, g_l);  cudaGetSymbolAddress((void**)&attnScr, g_attn);

    const long long ctxElems  = (long long)BATCH * SEQ * HID;
    const long long attnElems = (long long)BATCH * SEQ * SEQ;
    float* ctx  = out;
    float* attn = ((long long)out_size >= ctxElems + attnElems) ? out + ctxElems : attnScr;

    const long long XPZ = (long long)RALL * HID, WPZ = (long long)HID * HID;
    const float scale = 0.03125f;   // 1/sqrt(1024)

    // 1) convert inputs + weights to fp16
    split3<<<dim3((unsigned)(XPZ / 2048), 3), 256>>>(X[0], X[1], X[2], xh, XPZ);
    split3<<<dim3((unsigned)(WPZ / 2048), 3), 256>>>(W[0], W[1], W[2], wh, WPZ);

    // 2) projections (z = 0:Q, 1:K, 2:V), pure fp16
    ProjPtrs P;
    for (int i = 0; i < 3; ++i) {
        P.ah[i] = xh + i * XPZ;
        P.bh[i] = wh + i * WPZ;
        P.bias[i] = Bv[i];
        P.oh[i] = nullptr; P.of[i] = nullptr;
    }
    P.oh[0] = qh;
    P.oh[1] = kh;
    P.of[2] = vf;
    gemm_proj<<<dim3(8, 64, 3), 256, SMTOT>>>(P);

    // 3) V^T pack per batch: VT[b][h][s]
    pack_tr<<<dim3(32, 8, BATCH), 256>>>(vf, vth, HID,
        (long long)SEQ * HID, (long long)HID * SEQ, nullptr, nullptr, 0);

    // 4) scores: attn[b,s,t] = exp(scale * <K_s, Q_t>), causal; fused colsum
    cudaMemsetAsync(attn, 0, attnElems * sizeof(float), 0);
    cudaMemsetAsync(lsum, 0, BATCH * SEQ * sizeof(float), 0);
    gemm_scores<<<dim3(16, 16, BATCH), 256, SMTOT>>>(kh, qh, attn, lsum, scale);
    invert<<<BATCH * SEQ / 256, 256>>>(lsum);

    // 5) normalize attn in place + pack attn^T (fp16)
    pack_tr<<<dim3(32, 16, BATCH), 256>>>(attn, ath, SEQ,
        (long long)SEQ * SEQ, (long long)SEQ * SEQ, lsum, attn, 1);

    // 6) context: ctx[b,t,h] = sum_s AT[t,s]*VT[h,s]; heavy tiles split-K
    cudaMemsetAsync(ctx, 0, ctxElems * sizeof(float), 0);
    gemm_ctx<<<dim3(8, 24, BATCH), 256, SMTOT>>>(ath, vth, ctx);
}

// round 15
// speedup vs baseline: 6.5604x; 1.0969x over previous
#include <cuda_runtime.h>
#include <cuda_fp16.h>
#include <cstdint>

#define SEQ   2048
#define HID   1024
#define BATCH 4
#define RALL  (BATCH*SEQ)          // 8192

// ---------------- device scratch --------------------------------------------
__device__ __align__(16) __half g_xh[3][(long long)RALL*HID];
__device__ __align__(16) __half g_wh[3][HID*HID];
__device__ __align__(16) __half g_qh[(long long)RALL*HID];
__device__ __align__(16) __half g_kh[(long long)RALL*HID];
__device__ float g_vf[(long long)RALL*HID];
__device__ __align__(16) __half g_vth[(long long)RALL*HID];
__device__ __align__(16) __half g_ath[(long long)BATCH*SEQ*SEQ];
__device__ float g_attn[(long long)BATCH*SEQ*SEQ];
__device__ float g_l[BATCH*SEQ];

// ---------------- low-level helpers -----------------------------------------
__device__ __forceinline__ uint32_t smem_u32(const void* p){
    uint32_t a;
    asm("{ .reg .u64 t; cvta.to.shared.u64 t, %1; cvt.u32.u64 %0, t; }" : "=r"(a) : "l"(p));
    return a;
}
__device__ __forceinline__ void cp16(uint32_t d, const void* g){
    asm volatile("cp.async.cg.shared.global [%0], [%1], 16;" :: "r"(d), "l"(g));
}
__device__ __forceinline__ void ldm4(uint32_t* r, uint32_t a){
    asm volatile("ldmatrix.sync.aligned.m8n8.x4.shared.b16 {%0,%1,%2,%3}, [%4];"
        : "=r"(r[0]), "=r"(r[1]), "=r"(r[2]), "=r"(r[3]) : "r"(a));
}
__device__ __forceinline__ void mma16816(float* d, const uint32_t* a, const uint32_t* b){
    asm volatile("mma.sync.aligned.m16n8k16.row.col.f32.f16.f16.f32 "
        "{%0,%1,%2,%3}, {%4,%5,%6,%7}, {%8,%9}, {%0,%1,%2,%3};"
        : "+f"(d[0]), "+f"(d[1]), "+f"(d[2]), "+f"(d[3])
        : "r"(a[0]), "r"(a[1]), "r"(a[2]), "r"(a[3]), "r"(b[0]), "r"(b[1]));
}

#define BK     64
#define ROWH   72                  // fp16 elems per smem row (64 + 8 pad, 144B stride)
#define MATB   (128*ROWH*2)        // 18432 B per matrix tile
#define STAGEB (2*MATB)            // Ah, Bh = 36864 B
#define NSTAGE 2
#define SMTOT  (NSTAGE*STAGEB)     // 73728 B -> 2 CTAs/SM

// ---------------- shared GEMM body ------------------------------------------
// C[128x128]; NT: C[m,n] = sum_k A[m,k]*B[n,k]; pure fp16 operands, fp32 acc.
// K-chunks of 64. MODE: 0 = fp16 out + bias, 1 = exp(scale*v) causal -> fp32
// + fused colsum, 2 = fp32 out (optionally atomicAdd), 3 = fp32 + bias.
template<int MODE>
__device__ __forceinline__ void gemm_body(
    const __half* __restrict__ Ah, const __half* __restrict__ Bh,
    int ldA, int ldB, int m0, int n0, int kStart, int nK,
    const float* __restrict__ bias,
    float* __restrict__ Of, __half* __restrict__ Oh,
    int ldo, float scale, float* __restrict__ lsum, int atomicOut, char* smc)
{
    uint32_t sb = smem_u32(smc);
    int tid = threadIdx.x, lane = tid & 31, w = tid >> 5;
    int wm = w & 1, wn = w >> 1;                 // 2 x 4 warp grid (m x n)

    float acc[4][4][4];
    #pragma unroll
    for (int i = 0; i < 4; ++i)
        #pragma unroll
        for (int j = 0; j < 4; ++j)
            #pragma unroll
            for (int u = 0; u < 4; ++u) acc[i][j][u] = 0.f;

    int l15 = lane & 15;
    int aKsel = (lane >> 4) * 8;

#define LOADSTAGE(st, kb) {                                                    \
    int k0 = (kStart + (kb)) * BK;                                             \
    uint32_t so_ = sb + (st) * STAGEB;                                         \
    _Pragma("unroll") for (int i = 0; i < 4; ++i) {                            \
        int c = tid + i * 256; int row = c >> 3, seg = c & 7;                  \
        uint32_t sd = so_ + row * 144 + seg * 16;                              \
        long long ga = (long long)(m0 + row) * ldA + k0 + seg * 8;             \
        long long gb = (long long)(n0 + row) * ldB + k0 + seg * 8;             \
        cp16(sd,        Ah + ga);                                              \
        cp16(sd + MATB, Bh + gb);                                              \
    }                                                                          \
    asm volatile("cp.async.commit_group;"); }

    LOADSTAGE(0, 0);
    if (nK > 1) LOADSTAGE(1, 1);

    for (int kb = 0; kb < nK; ++kb) {
        int st = kb & 1;
        if (kb + 1 < nK) asm volatile("cp.async.wait_group 1;");
        else             asm volatile("cp.async.wait_group 0;");
        __syncthreads();

        uint32_t so = sb + st * STAGEB;
        #pragma unroll
        for (int ks = 0; ks < 4; ++ks) {
            uint32_t ah[4][4], bh[4][2];
            #pragma unroll
            for (int mi = 0; mi < 4; ++mi) {
                uint32_t off = ((wm*64 + mi*16 + l15) * ROWH + ks*16 + aKsel) * 2;
                ldm4(ah[mi], so + off);
            }
            #pragma unroll
            for (int np = 0; np < 2; ++np) {
                uint32_t off = ((wn*32 + np*16 + ((lane >> 4) << 3) + (lane & 7)) * ROWH
                                + ks*16 + ((lane >> 3) & 1) * 8) * 2;
                uint32_t t0[4];
                ldm4(t0, so + MATB + off);
                bh[2*np][0] = t0[0]; bh[2*np][1] = t0[1];
                bh[2*np+1][0] = t0[2]; bh[2*np+1][1] = t0[3];
            }
            #pragma unroll
            for (int mi = 0; mi < 4; ++mi)
                #pragma unroll
                for (int ni = 0; ni < 4; ++ni)
                    mma16816(acc[mi][ni], ah[mi], bh[ni]);
        }
        __syncthreads();
        if (kb + 2 < nK) LOADSTAGE(st, kb + 2);
    }
#undef LOADSTAGE

    // ---------------- epilogue ----------------
    float* cs = (float*)smc;             // per-CTA column sums (MODE 1)
    if (MODE == 1) {
        if (tid < 128) cs[tid] = 0.f;
        __syncthreads();
    }

    #pragma unroll
    for (int mi = 0; mi < 4; ++mi)
        #pragma unroll
        for (int ni = 0; ni < 4; ++ni) {
            int r0 = m0 + wm*64 + mi*16 + (lane >> 2);
            int cl = wn*32 + ni*8 + (lane & 3) * 2;
            int c  = n0 + cl;
            float s0 = 0.f, s1 = 0.f;
            #pragma unroll
            for (int hr = 0; hr < 2; ++hr) {
                int r = r0 + hr * 8;
                float v0 = acc[mi][ni][hr*2 + 0];
                float v1 = acc[mi][ni][hr*2 + 1];
                if (MODE == 0 || MODE == 3) { v0 += __ldg(bias + c); v1 += __ldg(bias + c + 1); }
                if (MODE == 1) {
                    v0 = (r <= c)     ? __expf(v0 * scale) : 0.f;
                    v1 = (r <= c + 1) ? __expf(v1 * scale) : 0.f;
                    s0 += v0; s1 += v1;
                }
                if (MODE == 0) {
                    *(__half2*)(Oh + (long long)r * ldo + c)
                        = __halves2half2(__float2half(v0), __float2half(v1));
                } else if (MODE == 2) {
                    float* p = Of + (long long)r * ldo + c;
                    if (atomicOut) { atomicAdd(p, v0); atomicAdd(p + 1, v1); }
                    else           *(float2*)p = make_float2(v0, v1);
                } else {
                    *(float2*)(Of + (long long)r * ldo + c) = make_float2(v0, v1);
                }
            }
            if (MODE == 1) { atomicAdd(&cs[cl], s0); atomicAdd(&cs[cl + 1], s1); }
        }

    if (MODE == 1) {
        __syncthreads();
        if (tid < 128) atomicAdd(&lsum[n0 + tid], cs[tid]);
    }
}

// ---------------- wrappers ---------------------------------------------------
struct ProjPtrs {
    const __half* ah[3];
    const __half* bh[3];
    const float*  bias[3];
    __half* oh[3]; float* of[3];
};

__global__ void __launch_bounds__(256, 2) gemm_proj(ProjPtrs P)
{
    int z = blockIdx.z;
    extern __shared__ __align__(16) char smc[];
    if (z == 2)
        gemm_body<3>(P.ah[2], P.bh[2], HID, HID,
                     blockIdx.y*128, blockIdx.x*128, 0, HID/BK, P.bias[2],
                     P.of[2], nullptr, HID, 1.f, nullptr, 0, smc);
    else
        gemm_body<0>(P.ah[z], P.bh[z], HID, HID,
                     blockIdx.y*128, blockIdx.x*128, 0, HID/BK, P.bias[z],
                     nullptr, P.oh[z], HID, 1.f, nullptr, 0, smc);
}

__global__ void __launch_bounds__(256, 2) gemm_scores(
    const __half* __restrict__ Kh, const __half* __restrict__ Qh,
    float* __restrict__ attn, float* __restrict__ lsum, float scale)
{
    int bz = blockIdx.z;
    float* att = attn + (long long)bz * SEQ * SEQ;
    if (blockIdx.y > blockIdx.x) {
        // fully-masked tile: write zeros (replaces global memset)
        int m0 = blockIdx.y * 128, n0 = blockIdx.x * 128;
        int tid = threadIdx.x;
        #pragma unroll
        for (int i = 0; i < 16; ++i) {
            int idx = tid + i * 256;               // 4096 float4 per tile
            int row = idx >> 5, c4 = idx & 31;
            *(float4*)(att + (long long)(m0 + row) * SEQ + n0 + c4 * 4)
                = make_float4(0.f, 0.f, 0.f, 0.f);
        }
        return;
    }
    extern __shared__ __align__(16) char smc[];
    long long z = (long long)bz * SEQ * HID;
    gemm_body<1>(Kh + z, Qh + z, HID, HID,
                 blockIdx.y*128, blockIdx.x*128, 0, HID/BK, nullptr,
                 att, nullptr, SEQ, scale, lsum + bz*SEQ, 0, smc);
}

__global__ void __launch_bounds__(256, 2) gemm_ctx(
    const __half* __restrict__ ATh, const __half* __restrict__ Vth,
    float* __restrict__ ctx)
{
    int by2 = blockIdx.y, bz = blockIdx.z;
    int by, half;
    if (by2 < 16) { by = 15 - (by2 >> 1); half = by2 & 1; }   // heavy tiles, split-K
    else          { by = 23 - by2;        half = -1;      }   // light tiles, full K
    int totK = 2 * (by + 1);                                  // chunks of 64
    int nK = (half >= 0) ? (totK >> 1) : totK;
    int kStart = (half > 0) ? nK : 0;
    extern __shared__ __align__(16) char smc[];
    gemm_body<2>(ATh + (long long)bz*SEQ*SEQ, Vth + (long long)bz*HID*SEQ,
                 SEQ, SEQ, by*128, blockIdx.x*128, kStart, nK, nullptr,
                 ctx + (long long)bz*SEQ*HID, nullptr, HID, 1.f,
                 nullptr, half >= 0 ? 1 : 0, smc);
}

// ---------------- fp32 -> fp16 convert (3 sources) ---------------------------
__global__ void split3(const float* __restrict__ s0, const float* __restrict__ s1,
                       const float* __restrict__ s2, __half* __restrict__ h,
                       long long perZ)
{
    int z = blockIdx.y;
    const float* s = (z == 0) ? s0 : ((z == 1) ? s1 : s2);
    long long i = ((long long)blockIdx.x * 256 + threadIdx.x) * 8;
    float4 a = *(const float4*)(s + i), b = *(const float4*)(s + i + 4);
    float v[8] = {a.x, a.y, a.z, a.w, b.x, b.y, b.z, b.w};
    union { uint4 u; __half e[8]; } H;
    #pragma unroll
    for (int j = 0; j < 8; ++j) H.e[j] = __float2half(v[j]);
    *(uint4*)(h + z * perZ + i) = H.u;
}

// ---------------- transpose + (optional) normalize + fp16 pack --------------
__global__ void pack_tr(const float* __restrict__ src, __half* __restrict__ dh,
                        int ldS, long long sZ, long long dZ,
                        const float* __restrict__ inv, float* __restrict__ wb, int causal)
{
    int kc = blockIdx.x, rt = blockIdx.y, bz = blockIdx.z;
    if (causal && kc * 64 > rt * 128 + 127) return;
    __shared__ float smt[64][129];
    const float* s = src + (long long)bz * sZ;
    int s0 = kc * 64, t0 = rt * 128;
    int tid = threadIdx.x;
    for (int i = 0; i < 32; ++i) {
        int idx = i * 256 + tid;
        int sr = idx >> 7, sc = idx & 127;
        float x = s[(long long)(s0 + sr) * ldS + t0 + sc];
        if (inv) {
            x *= inv[bz * SEQ + t0 + sc];
            wb[(long long)bz * sZ + (long long)(s0 + sr) * ldS + t0 + sc] = x;
        }
        smt[sr][sc] = x;
    }
    __syncthreads();
    int r = tid >> 1, half = tid & 1;
    long long db = (long long)bz * dZ + (long long)(t0 + r) * SEQ + s0 + half * 32;
    for (int g = 0; g < 4; ++g) {
        union { uint4 u; __half e[8]; } H;
        #pragma unroll
        for (int j = 0; j < 8; ++j)
            H.e[j] = __float2half(smt[half * 32 + g * 8 + j][r]);
        *(uint4*)(dh + db + g * 8) = H.u;
    }
}

__global__ void invert(float* __restrict__ l)
{
    int i = blockIdx.x * 256 + threadIdx.x;
    l[i] = 1.0f / l[i];
}

// ---------------- launch -----------------------------------------------------
extern "C" void kernel_launch(void* const* d_in, const int* in_sizes, int n_in,
                              void* d_out, int out_size)
{
    const float* X[3]  = {(const float*)d_in[0], (const float*)d_in[1], (const float*)d_in[2]};
    const float* W[3]  = {(const float*)d_in[3], (const float*)d_in[5], (const float*)d_in[7]};
    const float* Bv[3] = {(const float*)d_in[4], (const float*)d_in[6], (const float*)d_in[8]};
    float* out = (float*)d_out;

    cudaFuncSetAttribute(gemm_proj,   cudaFuncAttributeMaxDynamicSharedMemorySize, SMTOT);
    cudaFuncSetAttribute(gemm_scores, cudaFuncAttributeMaxDynamicSharedMemorySize, SMTOT);
    cudaFuncSetAttribute(gemm_ctx,    cudaFuncAttributeMaxDynamicSharedMemorySize, SMTOT);

    __half *xh, *wh, *qh, *kh, *vth, *ath;
    float *vf, *lsum, *attnScr;
    cudaGetSymbolAddress((void**)&xh, g_xh);   cudaGetSymbolAddress((void**)&wh, g_wh);
    cudaGetSymbolAddress((void**)&qh, g_qh);   cudaGetSymbolAddress((void**)&kh, g_kh);
    cudaGetSymbolAddress((void**)&vf, g_vf);   cudaGetSymbolAddress((void**)&vth, g_vth);
    cudaGetSymbolAddress((void**)&ath, g_ath);
    cudaGetSymbolAddress((void**)&lsum, g_l);  cudaGetSymbolAddress((void**)&attnScr, g_attn);

    const long long ctxElems  = (long long)BATCH * SEQ * HID;
    const long long attnElems = (long long)BATCH * SEQ * SEQ;
    float* ctx  = out;
    float* attn = ((long long)out_size >= ctxElems + attnElems) ? out + ctxElems : attnScr;

    const long long XPZ = (long long)RALL * HID, WPZ = (long long)HID * HID;
    const float scale = 0.03125f;   // 1/sqrt(1024)

    // 1) convert inputs + weights to fp16
    split3<<<dim3((unsigned)(XPZ / 2048), 3), 256>>>(X[0], X[1], X[2], xh, XPZ);
    split3<<<dim3((unsigned)(WPZ / 2048), 3), 256>>>(W[0], W[1], W[2], wh, WPZ);

    // 2) projections (z = 0:Q, 1:K, 2:V), pure fp16
    ProjPtrs P;
    for (int i = 0; i < 3; ++i) {
        P.ah[i] = xh + i * XPZ;
        P.bh[i] = wh + i * WPZ;
        P.bias[i] = Bv[i];
        P.oh[i] = nullptr; P.of[i] = nullptr;
    }
    P.oh[0] = qh;
    P.oh[1] = kh;
    P.of[2] = vf;
    gemm_proj<<<dim3(8, 64, 3), 256, SMTOT>>>(P);

    // 3) V^T pack per batch: VT[b][h][s]
    pack_tr<<<dim3(32, 8, BATCH), 256>>>(vf, vth, HID,
        (long long)SEQ * HID, (long long)HID * SEQ, nullptr, nullptr, 0);

    // 4) scores: attn[b,s,t] = exp(scale*<K_s,Q_t>) causal; masked tiles write 0
    cudaMemsetAsync(lsum, 0, BATCH * SEQ * sizeof(float), 0);
    gemm_scores<<<dim3(16, 16, BATCH), 256, SMTOT>>>(kh, qh, attn, lsum, scale);
    invert<<<BATCH * SEQ / 256, 256>>>(lsum);

    // 5) normalize attn in place + pack attn^T (fp16)
    pack_tr<<<dim3(32, 16, BATCH), 256>>>(attn, ath, SEQ,
        (long long)SEQ * SEQ, (long long)SEQ * SEQ, lsum, attn, 1);

    // 6) context: ctx[b,t,h] = sum_s AT[t,s]*VT[h,s]; heavy tiles split-K
    cudaMemsetAsync(ctx, 0, ctxElems * sizeof(float), 0);
    gemm_ctx<<<dim3(8, 24, BATCH), 256, SMTOT>>>(ath, vth, ctx);
}